// round 10
// baseline (speedup 1.0000x reference)
#include <cuda_runtime.h>
#include <cuda_bf16.h>

typedef unsigned long long u64;
typedef unsigned int u32;

#define Bn   2
#define Sn   1024
#define Hn   768
#define Dn   24
#define HIDn 96

// ---------------- scratch ----------------
__device__ float g_Zj  [Bn*Sn*Dn];
__device__ float g_Zi  [Bn*Sn*Dn];
__device__ float g_Cj  [Bn*Sn*HIDn];
__device__ float g_Ci  [Bn*Sn*HIDn];
__device__ float g_P   [Bn*Sn*Sn];
__device__ float g_ctxA[Bn*Sn*Hn];
__device__ float g_ctxB[Bn*Sn*Hn];
__device__ float g_h1A [Bn*Sn*Hn];
__device__ float g_h1B [Bn*Sn*Hn];
__device__ float g_h1C [Bn*Sn*Hn];

// ---------------- packed f32x2 helpers ----------------
__device__ __forceinline__ u64 pack2(float x, float y){
    u64 r;
    asm("mov.b64 %0, {%1, %2};" : "=l"(r)
        : "r"(__float_as_uint(x)), "r"(__float_as_uint(y)));
    return r;
}
__device__ __forceinline__ float2 unpack2(u64 v){
    unsigned lo, hi;
    asm("mov.b64 {%0, %1}, %2;" : "=r"(lo), "=r"(hi) : "l"(v));
    return make_float2(__uint_as_float(lo), __uint_as_float(hi));
}
__device__ __forceinline__ u64 fma2(u64 a, u64 b, u64 c){
    u64 d;
    asm("fma.rn.f32x2 %0, %1, %2, %3;" : "=l"(d) : "l"(a), "l"(b), "l"(c));
    return d;
}
__device__ __forceinline__ int swzB(int n){
    return ((n >> 2) & 1) * 64 + ((n >> 3) << 2) + (n & 3);
}
__device__ __forceinline__ u32 f2tf32(float f){
    u32 r;
    asm("cvt.rna.tf32.f32 %0, %1;" : "=r"(r) : "f"(f));
    return r;
}
__device__ __forceinline__ void mma_tf32(
    float& d0, float& d1, float& d2, float& d3,
    u32 a0, u32 a1, u32 a2, u32 a3, u32 b0, u32 b1)
{
    asm("mma.sync.aligned.m16n8k8.row.col.f32.tf32.tf32.f32 "
        "{%0,%1,%2,%3},{%4,%5,%6,%7},{%8,%9},{%0,%1,%2,%3};"
        : "+f"(d0), "+f"(d1), "+f"(d2), "+f"(d3)
        : "r"(a0), "r"(a1), "r"(a2), "r"(a3), "r"(b0), "r"(b1));
}

// =================== kernel 1: projections + per-token MLP terms ===================
__global__ __launch_bounds__(256) void k_proj(
    const float* __restrict__ Hj, const float* __restrict__ Hi,
    const float* __restrict__ Wpj, const float* __restrict__ Wpi,
    const float* __restrict__ Ws1, const float* __restrict__ bs1)
{
    __shared__ float shj[Hn], shi[Hn];
    __shared__ float sz[48];
    __shared__ float sws1[96][97];
    const int row = blockIdx.x;
    const int t = threadIdx.x;
    const float* hj = Hj + (size_t)row*Hn;
    const float* hi = Hi + (size_t)row*Hn;
    for (int k = t; k < Hn; k += 256){ shj[k] = hj[k]; shi[k] = hi[k]; }
    for (int idx = t; idx < 96*96; idx += 256) sws1[idx/96][idx%96] = Ws1[idx];
    __syncthreads();

    const int w = t >> 5, lane = t & 31;
    for (int o = w; o < 48; o += 8){
        const float* wv = (o < 24) ? (Wpj + (size_t)o*Hn) : (Wpi + (size_t)(o-24)*Hn);
        const float* x  = (o < 24) ? shj : shi;
        float s0 = 0.f, s1 = 0.f;
        #pragma unroll
        for (int h = lane; h < Hn; h += 64){
            s0 = fmaf(wv[h],    x[h],    s0);
            s1 = fmaf(wv[h+32], x[h+32], s1);
        }
        float s = s0 + s1;
        #pragma unroll
        for (int off = 16; off; off >>= 1) s += __shfl_xor_sync(0xffffffffu, s, off);
        if (lane == 0){
            sz[o] = s;
            if (o < 24) g_Zj[(size_t)row*24 + o]      = s;
            else        g_Zi[(size_t)row*24 + (o-24)] = s;
        }
    }
    __syncthreads();

    if (t < 192){
        int h = (t < 96) ? t : t - 96;
        const float* z  = (t < 96) ? sz : (sz + 24);
        const float* wr = &sws1[h][(t < 96) ? 0 : 24];
        float s = (t < 96) ? 0.f : bs1[h];
        #pragma unroll
        for (int d = 0; d < 24; d++) s = fmaf(wr[d], z[d], s);
        if (t < 96) g_Cj[(size_t)row*96 + h] = s;
        else        g_Ci[(size_t)row*96 + h] = s;
    }
}

// =================== kernel 2: pair MLP via tf32 mma.sync ===================
// Ci in registers (j-invariant per-thread slice), 1 CTA/SM (no reg cap -> no spills),
// mma chains split 3+3 for 2x ILP.
#define JT 128
#define IT 128

#define OFF_ASW  0                          // 1152 uint4  = 18432
#define OFF_BSW  18432                      // 2*3072 uint2 = 49152
#define OFF_ZI   (18432+49152)              // 128*25 f = 12800
#define OFF_ZJ   (OFF_ZI+12800)             // 128*25 f = 12800
#define OFF_CJ   (OFF_ZJ+12800)             // 2*96 f = 768
#define SMEM_PAIR (OFF_CJ+768)

__global__ __launch_bounds__(256) void k_pair_mma(
    const float* __restrict__ Ws1, const float* __restrict__ Ws2,
    const float* __restrict__ bs2)
{
    extern __shared__ __align__(16) char smem[];
    uint4* Asw  = (uint4*)(smem + OFF_ASW);
    uint2* Bsw  = (uint2*)(smem + OFF_BSW);
    float* Zi_s = (float*)(smem + OFF_ZI);
    float* Zj_s = (float*)(smem + OFF_ZJ);
    float* Cj_s = (float*)(smem + OFF_CJ);

    const int t  = threadIdx.x;
    const int i0 = blockIdx.x * IT;
    const int j0 = blockIdx.y * JT;
    const int b  = blockIdx.z;
    const int base = b * Sn;
    const int w = t >> 5, lane = t & 31;
    const int g = lane >> 2, t4 = lane & 3;

    for (int idx = t; idx < 1152; idx += 256){
        int mt = idx / 192, r = idx % 192, kt = r / 32, ln = r % 32;
        int gg = ln >> 2, tt = ln & 3;
        int h = mt*16 + gg, k = kt*8 + tt;
        uint4 v;
        v.x = f2tf32(Ws1[h*96 + 48 + k]);
        v.y = f2tf32(Ws1[(h+8)*96 + 48 + k]);
        v.z = f2tf32(Ws1[h*96 + 48 + k + 4]);
        v.w = f2tf32(Ws1[(h+8)*96 + 48 + k + 4]);
        Asw[idx] = v;
    }
    for (int idx = t; idx < IT*24; idx += 256){
        int r = idx / 24, k = idx % 24;
        Zi_s[r*25 + k] = g_Zi[(size_t)(base + i0 + r)*24 + k];
    }
    for (int idx = t; idx < JT*24; idx += 256){
        int r = idx / 24, k = idx % 24;
        Zj_s[r*25 + k] = g_Zj[(size_t)(base + j0 + r)*24 + k];
    }
    const float bs2v = bs2[0];
    float ws[6][2];
    #pragma unroll
    for (int mt = 0; mt < 6; mt++){
        ws[mt][0] = Ws2[mt*16 + g];
        ws[mt][1] = Ws2[mt*16 + g + 8];
    }
    // preload this thread's Ci slice (j-invariant)
    const int ccol = w*16 + 2*t4;
    float ci[6][2][4];
    #pragma unroll
    for (int mt = 0; mt < 6; mt++)
        #pragma unroll
        for (int nt = 0; nt < 2; nt++){
            const int c  = ccol + nt*8;
            const int h0 = mt*16 + g;
            const float* r0 = &g_Ci[(size_t)(base + i0 + c)*96];
            const float* r1 = &g_Ci[(size_t)(base + i0 + c + 1)*96];
            ci[mt][nt][0] = r0[h0];
            ci[mt][nt][1] = r1[h0];
            ci[mt][nt][2] = r0[h0 + 8];
            ci[mt][nt][3] = r1[h0 + 8];
        }
    __syncthreads();

    auto build = [&](int jn, int p){
        if (t < 96) Cj_s[p*96 + t] = g_Cj[(size_t)(base + j0 + jn)*96 + t];
        const float* zj = &Zj_s[jn*25];
        uint2* dst = Bsw + p*3072;
        #pragma unroll
        for (int q = 0; q < 12; q++){
            int e = t + q*256;
            int kt = e >> 9, ww = (e >> 6) & 7, nt = (e >> 5) & 1, ln = e & 31;
            int gg = ln >> 2, tt = ln & 3;
            int col = ww*16 + nt*8 + gg;
            int k0 = kt*8 + tt, k1 = k0 + 4;
            const float* zi = &Zi_s[col*25];
            float f0, f1;
            if (kt < 3){ f0 = zj[k0]*zi[k0]; f1 = zj[k1]*zi[k1]; }
            else { f0 = fabsf(zj[k0-24] - zi[k0-24]); f1 = fabsf(zj[k1-24] - zi[k1-24]); }
            uint2 u; u.x = f2tf32(f0); u.y = f2tf32(f1);
            dst[e] = u;
        }
    };

    build(0, 0);
    __syncthreads();

    for (int jj = 0; jj < JT; jj++){
        const int p = jj & 1;
        if (jj + 1 < JT) build(jj + 1, p ^ 1);

        float cj[6][2];
        #pragma unroll
        for (int mt = 0; mt < 6; mt++){
            cj[mt][0] = Cj_s[p*96 + mt*16 + g];
            cj[mt][1] = Cj_s[p*96 + mt*16 + g + 8];
        }
        u32 bf[2][6][2];
        #pragma unroll
        for (int nt = 0; nt < 2; nt++)
            #pragma unroll
            for (int kt = 0; kt < 6; kt++){
                uint2 u = Bsw[p*3072 + ((kt*8 + w)*2 + nt)*32 + lane];
                bf[nt][kt][0] = u.x; bf[nt][kt][1] = u.y;
            }

        float pA[4] = {0.f, 0.f, 0.f, 0.f};
        #pragma unroll
        for (int mt = 0; mt < 6; mt++){
            uint4 af[6];
            #pragma unroll
            for (int kt = 0; kt < 6; kt++) af[kt] = Asw[(mt*6 + kt)*32 + lane];
            #pragma unroll
            for (int nt = 0; nt < 2; nt++){
                // two independent 3-deep chains (2x ILP), summed exactly after
                float d0 = 0.f, d1 = 0.f, d2 = 0.f, d3 = 0.f;
                float e0 = 0.f, e1 = 0.f, e2 = 0.f, e3 = 0.f;
                #pragma unroll
                for (int kt = 0; kt < 3; kt++)
                    mma_tf32(d0, d1, d2, d3,
                             af[kt].x, af[kt].y, af[kt].z, af[kt].w,
                             bf[nt][kt][0], bf[nt][kt][1]);
                #pragma unroll
                for (int kt = 3; kt < 6; kt++)
                    mma_tf32(e0, e1, e2, e3,
                             af[kt].x, af[kt].y, af[kt].z, af[kt].w,
                             bf[nt][kt][0], bf[nt][kt][1]);
                d0 += e0; d1 += e1; d2 += e2; d3 += e3;
                float v0 = fmaxf(d0 + cj[mt][0] + ci[mt][nt][0], 0.f);
                float v1 = fmaxf(d1 + cj[mt][0] + ci[mt][nt][1], 0.f);
                float v2 = fmaxf(d2 + cj[mt][1] + ci[mt][nt][2], 0.f);
                float v3 = fmaxf(d3 + cj[mt][1] + ci[mt][nt][3], 0.f);
                pA[nt*2]   = fmaf(ws[mt][0], v0, fmaf(ws[mt][1], v2, pA[nt*2]));
                pA[nt*2+1] = fmaf(ws[mt][0], v1, fmaf(ws[mt][1], v3, pA[nt*2+1]));
            }
        }
        #pragma unroll
        for (int q = 0; q < 4; q++){
            pA[q] += __shfl_xor_sync(0xffffffffu, pA[q], 4);
            pA[q] += __shfl_xor_sync(0xffffffffu, pA[q], 8);
            pA[q] += __shfl_xor_sync(0xffffffffu, pA[q], 16);
        }
        if (g == 0){
            float* dst = &g_P[(size_t)(base + j0 + jj)*Sn + i0 + w*16];
            *(float2*)(dst + 2*t4)     = make_float2(pA[0] + bs2v, pA[1] + bs2v);
            *(float2*)(dst + 8 + 2*t4) = make_float2(pA[2] + bs2v, pA[3] + bs2v);
        }
        __syncthreads();
    }
}

// =================== kernel 3: masked softmax over i (in place) ===================
__global__ __launch_bounds__(256) void k_softmax(const float* __restrict__ mask){
    const int r = blockIdx.x;
    const int b = r / Sn;
    float* row = g_P + (size_t)r*Sn;
    const float* mrow = mask + (size_t)b*Sn;
    const int t = threadIdx.x;
    __shared__ float red[256];

    float vals[4]; float mx = -3.402823466e38f;
    #pragma unroll
    for (int q = 0; q < 4; q++){
        int i = t + q*256;
        float v = row[i] + (1.0f - mrow[i]) * (-3.402823466e38f);
        vals[q] = v; mx = fmaxf(mx, v);
    }
    red[t] = mx; __syncthreads();
    for (int s = 128; s > 0; s >>= 1){ if (t < s) red[t] = fmaxf(red[t], red[t+s]); __syncthreads(); }
    mx = red[0]; __syncthreads();

    float sum = 0.f;
    #pragma unroll
    for (int q = 0; q < 4; q++){ vals[q] = __expf(vals[q] - mx); sum += vals[q]; }
    red[t] = sum; __syncthreads();
    for (int s = 128; s > 0; s >>= 1){ if (t < s) red[t] += red[t+s]; __syncthreads(); }
    float inv = 1.0f / red[0];
    #pragma unroll
    for (int q = 0; q < 4; q++) row[t + q*256] = vals[q] * inv;
}

// =================== balanced f32x2 GEMM ===================
// MODE 0: ctx partial = P[:, ks] @ Hi[ks, :]        (K=512, ks in {0,1}, per batch)
// MODE 1: h1 partial  (K=768 per slice, ks in {0,1,2}: ctx / Hj / ctx*Hj)
// MODE 2: out = alpha*( relu(h1A+h1B+h1C+bv1) @ Wv2^T + bv2 )  (K=768)
template<int MODE>
__global__ __launch_bounds__(128) void k_gemm(
    const float* __restrict__ BW,
    const float* __restrict__ Hj,
    const float* __restrict__ bias,    // MODE2: bv1
    const float* __restrict__ bias2,   // MODE2: bv2
    const float* __restrict__ alpha_p,
    float* __restrict__ Cout)
{
    constexpr int KH = (MODE == 0) ? 512 : 768;
    constexpr int T  = KH / 16;
    __shared__ __align__(16) float As[2][16][64];
    __shared__ __align__(16) float Bs[2][16][128];

    const int t  = threadIdx.x;
    const int n0 = blockIdx.x * 128;
    const int m0 = blockIdx.y * 64;
    int b = 0, ks = 0;
    if (MODE == 0){ b = blockIdx.z >> 1; ks = blockIdx.z & 1; }
    if (MODE == 1){ ks = blockIdx.z; }
    const int rowbase = (MODE == 0) ? b*Sn + m0 : m0;
    const int kbase   = ks * KH;

    const int am = t >> 1, ah8 = (t & 1) * 8;
    const int b0r = t >> 3, b0q = (t & 7);
    const int ty = t >> 4, tx = t & 15;
    const int swt = swzB(t & 127);

    const float* ArowP  = g_P    + (size_t)(rowbase + am)*Sn + kbase;
    const float* ArowCA = g_ctxA + (size_t)(rowbase + am)*Hn;
    const float* ArowCB = g_ctxB + (size_t)(rowbase + am)*Hn;
    const float* ArowH  = (MODE == 1) ? (Hj + (size_t)(rowbase + am)*Hn) : (const float*)0;
    const float* ArowA  = g_h1A  + (size_t)(rowbase + am)*Hn;
    const float* ArowB  = g_h1B  + (size_t)(rowbase + am)*Hn;
    const float* ArowC  = g_h1C  + (size_t)(rowbase + am)*Hn;
    const float* Bsrc   = (MODE == 0) ? (BW + (size_t)b*Sn*Hn) : BW;

    float4 ra0, ra1, rb0, rb1, rb2, rb3;

    auto ldg = [&](int kt){
        const int kb = kt * 16;
        if (MODE == 0){
            ra0 = *(const float4*)(ArowP + kb + ah8);
            ra1 = *(const float4*)(ArowP + kb + ah8 + 4);
        } else if (MODE == 2){
            const int fo = kb + ah8;
            float4 xa0 = *(const float4*)(ArowA + fo);
            float4 xa1 = *(const float4*)(ArowA + fo + 4);
            float4 xb0 = *(const float4*)(ArowB + fo);
            float4 xb1 = *(const float4*)(ArowB + fo + 4);
            float4 xc0 = *(const float4*)(ArowC + fo);
            float4 xc1 = *(const float4*)(ArowC + fo + 4);
            float4 bb0 = *(const float4*)(bias + fo);
            float4 bb1 = *(const float4*)(bias + fo + 4);
            ra0 = make_float4(fmaxf(xa0.x+xb0.x+xc0.x+bb0.x,0.f), fmaxf(xa0.y+xb0.y+xc0.y+bb0.y,0.f),
                              fmaxf(xa0.z+xb0.z+xc0.z+bb0.z,0.f), fmaxf(xa0.w+xb0.w+xc0.w+bb0.w,0.f));
            ra1 = make_float4(fmaxf(xa1.x+xb1.x+xc1.x+bb1.x,0.f), fmaxf(xa1.y+xb1.y+xc1.y+bb1.y,0.f),
                              fmaxf(xa1.z+xb1.z+xc1.z+bb1.z,0.f), fmaxf(xa1.w+xb1.w+xc1.w+bb1.w,0.f));
        } else { // MODE 1: slice by ks
            const int fo = kb + ah8;
            if (ks == 0){
                float4 c0 = *(const float4*)(ArowCA + fo);
                float4 c1 = *(const float4*)(ArowCA + fo + 4);
                float4 d0 = *(const float4*)(ArowCB + fo);
                float4 d1 = *(const float4*)(ArowCB + fo + 4);
                ra0 = make_float4(c0.x+d0.x, c0.y+d0.y, c0.z+d0.z, c0.w+d0.w);
                ra1 = make_float4(c1.x+d1.x, c1.y+d1.y, c1.z+d1.z, c1.w+d1.w);
            } else if (ks == 1){
                ra0 = *(const float4*)(ArowH + fo);
                ra1 = *(const float4*)(ArowH + fo + 4);
            } else {
                float4 c0 = *(const float4*)(ArowCA + fo);
                float4 c1 = *(const float4*)(ArowCA + fo + 4);
                float4 d0 = *(const float4*)(ArowCB + fo);
                float4 d1 = *(const float4*)(ArowCB + fo + 4);
                float4 h0 = *(const float4*)(ArowH + fo);
                float4 h1 = *(const float4*)(ArowH + fo + 4);
                ra0 = make_float4((c0.x+d0.x)*h0.x, (c0.y+d0.y)*h0.y,
                                  (c0.z+d0.z)*h0.z, (c0.w+d0.w)*h0.w);
                ra1 = make_float4((c1.x+d1.x)*h1.x, (c1.y+d1.y)*h1.y,
                                  (c1.z+d1.z)*h1.z, (c1.w+d1.w)*h1.w);
            }
        }
        if (MODE == 0){
            const float* s = Bsrc + (size_t)(kbase + kb + b0r)*Hn + n0 + b0q*16;
            rb0 = *(const float4*)s;       rb1 = *(const float4*)(s + 4);
            rb2 = *(const float4*)(s + 8); rb3 = *(const float4*)(s + 12);
        } else {
            constexpr int KW = (MODE == 1) ? 2304 : 768;
            const float* s = Bsrc + (size_t)(n0 + t)*KW + kbase + kb;
            rb0 = *(const float4*)s;       rb1 = *(const float4*)(s + 4);
            rb2 = *(const float4*)(s + 8); rb3 = *(const float4*)(s + 12);
        }
    };
    auto sts = [&](int buf){
        float* Af = &As[buf][0][0];
        Af[(ah8+0)*64 + am] = ra0.x; Af[(ah8+1)*64 + am] = ra0.y;
        Af[(ah8+2)*64 + am] = ra0.z; Af[(ah8+3)*64 + am] = ra0.w;
        Af[(ah8+4)*64 + am] = ra1.x; Af[(ah8+5)*64 + am] = ra1.y;
        Af[(ah8+6)*64 + am] = ra1.z; Af[(ah8+7)*64 + am] = ra1.w;
        if (MODE == 0){
            float* d = &Bs[buf][b0r][0];
            *(float4*)(d + 8*b0q)          = rb0;
            *(float4*)(d + 64 + 8*b0q)     = rb1;
            *(float4*)(d + 8*b0q + 4)      = rb2;
            *(float4*)(d + 64 + 8*b0q + 4) = rb3;
        } else {
            Bs[buf][ 0][swt] = rb0.x; Bs[buf][ 1][swt] = rb0.y;
            Bs[buf][ 2][swt] = rb0.z; Bs[buf][ 3][swt] = rb0.w;
            Bs[buf][ 4][swt] = rb1.x; Bs[buf][ 5][swt] = rb1.y;
            Bs[buf][ 6][swt] = rb1.z; Bs[buf][ 7][swt] = rb1.w;
            Bs[buf][ 8][swt] = rb2.x; Bs[buf][ 9][swt] = rb2.y;
            Bs[buf][10][swt] = rb2.z; Bs[buf][11][swt] = rb2.w;
            Bs[buf][12][swt] = rb3.x; Bs[buf][13][swt] = rb3.y;
            Bs[buf][14][swt] = rb3.z; Bs[buf][15][swt] = rb3.w;
        }
    };

    u64 acc[4][8];
    #pragma unroll
    for (int m = 0; m < 4; m++)
        #pragma unroll
        for (int n = 0; n < 8; n++) acc[m][n] = 0ull;

    ldg(0); sts(0); __syncthreads();

    for (int tt = 0; tt < T; tt++){
        const int cur = tt & 1;
        if (tt + 1 < T) ldg(tt + 1);
        #pragma unroll
        for (int k = 0; k < 16; k++){
            ulonglong2 A01 = *(const ulonglong2*)&As[cur][k][ty*8];
            ulonglong2 A23 = *(const ulonglong2*)&As[cur][k][ty*8 + 4];
            float4 bq0 = *(const float4*)&Bs[cur][k][tx*4];
            float4 bq1 = *(const float4*)&Bs[cur][k][64 + tx*4];
            u64 av[4] = {A01.x, A01.y, A23.x, A23.y};
            u64 bd[8] = {pack2(bq0.x,bq0.x), pack2(bq0.y,bq0.y),
                         pack2(bq0.z,bq0.z), pack2(bq0.w,bq0.w),
                         pack2(bq1.x,bq1.x), pack2(bq1.y,bq1.y),
                         pack2(bq1.z,bq1.z), pack2(bq1.w,bq1.w)};
            #pragma unroll
            for (int m = 0; m < 4; m++)
                #pragma unroll
                for (int n = 0; n < 8; n++)
                    acc[m][n] = fma2(av[m], bd[n], acc[m][n]);
        }
        if (tt + 1 < T) sts(cur ^ 1);
        __syncthreads();
    }

    const float alpha = (MODE == 2) ? alpha_p[0] : 1.0f;
    const int nbase = n0 + tx*8;
    float badd[8];
    if (MODE == 2){
        float4 v0 = *(const float4*)(bias2 + nbase);
        float4 v1 = *(const float4*)(bias2 + nbase + 4);
        badd[0]=v0.x; badd[1]=v0.y; badd[2]=v0.z; badd[3]=v0.w;
        badd[4]=v1.x; badd[5]=v1.y; badd[6]=v1.z; badd[7]=v1.w;
    }
    #pragma unroll
    for (int r = 0; r < 8; r++){
        const int mp = r >> 1, part = r & 1;
        float out[8];
        #pragma unroll
        for (int q = 0; q < 8; q++){
            float2 v = unpack2(acc[mp][q]);
            out[q] = part ? v.y : v.x;
        }
        if (MODE == 2){
            #pragma unroll
            for (int q = 0; q < 8; q++) out[q] = (out[q] + badd[q]) * alpha;
        }
        float* dst;
        const size_t roff = (size_t)(rowbase + ty*8 + r)*Hn + nbase;
        if      (MODE == 0) dst = (ks == 0 ? g_ctxA : g_ctxB) + roff;
        else if (MODE == 1) dst = (ks == 0 ? g_h1A : (ks == 1 ? g_h1B : g_h1C)) + roff;
        else                dst = Cout + roff;
        *(float4*)dst       = *(float4*)&out[0];
        *(float4*)(dst + 4) = *(float4*)&out[4];
    }
}

// =============================== launch ===============================
extern "C" void kernel_launch(void* const* d_in, const int* in_sizes, int n_in,
                              void* d_out, int out_size)
{
    const float* Hj    = (const float*)d_in[0];
    const float* Hi    = (const float*)d_in[1];
    const float* mask  = (const float*)d_in[2];
    const float* Wpj   = (const float*)d_in[3];
    const float* Wpi   = (const float*)d_in[4];
    const float* Ws1   = (const float*)d_in[5];
    const float* bs1   = (const float*)d_in[6];
    const float* Ws2   = (const float*)d_in[7];
    const float* bs2   = (const float*)d_in[8];
    const float* Wv1   = (const float*)d_in[9];
    const float* bv1   = (const float*)d_in[10];
    const float* Wv2   = (const float*)d_in[11];
    const float* bv2   = (const float*)d_in[12];
    const float* alpha = (const float*)d_in[13];
    float* out = (float*)d_out;

    cudaFuncSetAttribute(k_pair_mma, cudaFuncAttributeMaxDynamicSharedMemorySize, SMEM_PAIR);

    k_proj<<<Bn*Sn, 256>>>(Hj, Hi, Wpj, Wpi, Ws1, bs1);

    dim3 gp(Sn/IT, Sn/JT, Bn);
    k_pair_mma<<<gp, 256, SMEM_PAIR>>>(Ws1, Ws2, bs2);

    k_softmax<<<Bn*Sn, 256>>>(mask);

    dim3 g0(Hn/128, Sn/64, Bn*2);
    k_gemm<0><<<g0, 128>>>(Hi, nullptr, nullptr, nullptr, nullptr, nullptr);

    dim3 g1(Hn/128, (Bn*Sn)/64, 3);
    k_gemm<1><<<g1, 128>>>(Wv1, Hj, nullptr, nullptr, nullptr, nullptr);

    dim3 g2(Hn/128, (Bn*Sn)/64, 1);
    k_gemm<2><<<g2, 128>>>(Wv2, nullptr, bv1, bv2, alpha, out);
}

// round 11
// speedup vs baseline: 1.0264x; 1.0264x over previous
#include <cuda_runtime.h>
#include <cuda_bf16.h>

typedef unsigned long long u64;
typedef unsigned int u32;

#define Bn   2
#define Sn   1024
#define Hn   768
#define Dn   24
#define HIDn 96

// ---------------- scratch ----------------
__device__ float g_Zj  [Bn*Sn*Dn];
__device__ float g_Zi  [Bn*Sn*Dn];
__device__ float g_Cj  [Bn*Sn*HIDn];
__device__ float g_Ci  [Bn*Sn*HIDn];
__device__ float g_P   [Bn*Sn*Sn];
__device__ float g_ctxA[Bn*Sn*Hn];
__device__ float g_ctxB[Bn*Sn*Hn];
__device__ float g_h1A [Bn*Sn*Hn];
__device__ float g_h1B [Bn*Sn*Hn];
__device__ float g_h1C [Bn*Sn*Hn];

// ---------------- packed f32x2 helpers ----------------
__device__ __forceinline__ u64 pack2(float x, float y){
    u64 r;
    asm("mov.b64 %0, {%1, %2};" : "=l"(r)
        : "r"(__float_as_uint(x)), "r"(__float_as_uint(y)));
    return r;
}
__device__ __forceinline__ float2 unpack2(u64 v){
    unsigned lo, hi;
    asm("mov.b64 {%0, %1}, %2;" : "=r"(lo), "=r"(hi) : "l"(v));
    return make_float2(__uint_as_float(lo), __uint_as_float(hi));
}
__device__ __forceinline__ u64 fma2(u64 a, u64 b, u64 c){
    u64 d;
    asm("fma.rn.f32x2 %0, %1, %2, %3;" : "=l"(d) : "l"(a), "l"(b), "l"(c));
    return d;
}
__device__ __forceinline__ int swzB(int n){
    return ((n >> 2) & 1) * 64 + ((n >> 3) << 2) + (n & 3);
}
__device__ __forceinline__ u32 f2tf32(float f){
    u32 r;
    asm("cvt.rna.tf32.f32 %0, %1;" : "=r"(r) : "f"(f));
    return r;
}
__device__ __forceinline__ void mma_tf32(
    float& d0, float& d1, float& d2, float& d3,
    u32 a0, u32 a1, u32 a2, u32 a3, u32 b0, u32 b1)
{
    asm("mma.sync.aligned.m16n8k8.row.col.f32.tf32.tf32.f32 "
        "{%0,%1,%2,%3},{%4,%5,%6,%7},{%8,%9},{%0,%1,%2,%3};"
        : "+f"(d0), "+f"(d1), "+f"(d2), "+f"(d3)
        : "r"(a0), "r"(a1), "r"(a2), "r"(a3), "r"(b0), "r"(b1));
}

// =================== kernel 1: projections + per-token MLP terms ===================
__global__ __launch_bounds__(256) void k_proj(
    const float* __restrict__ Hj, const float* __restrict__ Hi,
    const float* __restrict__ Wpj, const float* __restrict__ Wpi,
    const float* __restrict__ Ws1, const float* __restrict__ bs1)
{
    __shared__ float shj[Hn], shi[Hn];
    __shared__ float sz[48];
    __shared__ float sws1[96][97];
    const int row = blockIdx.x;
    const int t = threadIdx.x;
    const float* hj = Hj + (size_t)row*Hn;
    const float* hi = Hi + (size_t)row*Hn;
    for (int k = t; k < Hn; k += 256){ shj[k] = hj[k]; shi[k] = hi[k]; }
    for (int idx = t; idx < 96*96; idx += 256) sws1[idx/96][idx%96] = Ws1[idx];
    __syncthreads();

    const int w = t >> 5, lane = t & 31;
    for (int o = w; o < 48; o += 8){
        const float* wv = (o < 24) ? (Wpj + (size_t)o*Hn) : (Wpi + (size_t)(o-24)*Hn);
        const float* x  = (o < 24) ? shj : shi;
        float s0 = 0.f, s1 = 0.f;
        #pragma unroll
        for (int h = lane; h < Hn; h += 64){
            s0 = fmaf(wv[h],    x[h],    s0);
            s1 = fmaf(wv[h+32], x[h+32], s1);
        }
        float s = s0 + s1;
        #pragma unroll
        for (int off = 16; off; off >>= 1) s += __shfl_xor_sync(0xffffffffu, s, off);
        if (lane == 0){
            sz[o] = s;
            if (o < 24) g_Zj[(size_t)row*24 + o]      = s;
            else        g_Zi[(size_t)row*24 + (o-24)] = s;
        }
    }
    __syncthreads();

    if (t < 192){
        int h = (t < 96) ? t : t - 96;
        const float* z  = (t < 96) ? sz : (sz + 24);
        const float* wr = &sws1[h][(t < 96) ? 0 : 24];
        float s = (t < 96) ? 0.f : bs1[h];
        #pragma unroll
        for (int d = 0; d < 24; d++) s = fmaf(wr[d], z[d], s);
        if (t < 96) g_Cj[(size_t)row*96 + h] = s;
        else        g_Ci[(size_t)row*96 + h] = s;
    }
}

// =================== kernel 2: pair MLP via tf32 mma.sync (R7 version: Ci in smem) ===================
#define JT 128
#define IT 128

#define OFF_ASW  0                          // 1152 uint4  = 18432
#define OFF_BSW  18432                      // 2*3072 uint2 = 49152
#define OFF_CI   (18432+49152)              // 128*100 f   = 51200
#define OFF_ZI   (OFF_CI+51200)             // 128*25  f   = 12800
#define OFF_ZJ   (OFF_ZI+12800)             // 128*25  f   = 12800
#define OFF_CJ   (OFF_ZJ+12800)             // 2*96    f   = 768
#define SMEM_PAIR (OFF_CJ+768)

__global__ __launch_bounds__(256) void k_pair_mma(
    const float* __restrict__ Ws1, const float* __restrict__ Ws2,
    const float* __restrict__ bs2)
{
    extern __shared__ __align__(16) char smem[];
    uint4* Asw  = (uint4*)(smem + OFF_ASW);
    uint2* Bsw  = (uint2*)(smem + OFF_BSW);
    float* Ci_s = (float*)(smem + OFF_CI);
    float* Zi_s = (float*)(smem + OFF_ZI);
    float* Zj_s = (float*)(smem + OFF_ZJ);
    float* Cj_s = (float*)(smem + OFF_CJ);

    const int t  = threadIdx.x;
    const int i0 = blockIdx.x * IT;
    const int j0 = blockIdx.y * JT;
    const int b  = blockIdx.z;
    const int base = b * Sn;
    const int w = t >> 5, lane = t & 31;
    const int g = lane >> 2, t4 = lane & 3;

    for (int idx = t; idx < 1152; idx += 256){
        int mt = idx / 192, r = idx % 192, kt = r / 32, ln = r % 32;
        int gg = ln >> 2, tt = ln & 3;
        int h = mt*16 + gg, k = kt*8 + tt;
        uint4 v;
        v.x = f2tf32(Ws1[h*96 + 48 + k]);
        v.y = f2tf32(Ws1[(h+8)*96 + 48 + k]);
        v.z = f2tf32(Ws1[h*96 + 48 + k + 4]);
        v.w = f2tf32(Ws1[(h+8)*96 + 48 + k + 4]);
        Asw[idx] = v;
    }
    for (int idx = t; idx < IT*96; idx += 256){
        int r = idx / 96, h = idx % 96;
        Ci_s[r*100 + h] = g_Ci[(size_t)(base + i0 + r)*96 + h];
    }
    for (int idx = t; idx < IT*24; idx += 256){
        int r = idx / 24, k = idx % 24;
        Zi_s[r*25 + k] = g_Zi[(size_t)(base + i0 + r)*24 + k];
    }
    for (int idx = t; idx < JT*24; idx += 256){
        int r = idx / 24, k = idx % 24;
        Zj_s[r*25 + k] = g_Zj[(size_t)(base + j0 + r)*24 + k];
    }
    const float bs2v = bs2[0];
    float ws[6][2];
    #pragma unroll
    for (int mt = 0; mt < 6; mt++){
        ws[mt][0] = Ws2[mt*16 + g];
        ws[mt][1] = Ws2[mt*16 + g + 8];
    }
    __syncthreads();

    auto build = [&](int jn, int p){
        if (t < 96) Cj_s[p*96 + t] = g_Cj[(size_t)(base + j0 + jn)*96 + t];
        const float* zj = &Zj_s[jn*25];
        uint2* dst = Bsw + p*3072;
        #pragma unroll
        for (int q = 0; q < 12; q++){
            int e = t + q*256;
            int kt = e >> 9, ww = (e >> 6) & 7, nt = (e >> 5) & 1, ln = e & 31;
            int gg = ln >> 2, tt = ln & 3;
            int col = ww*16 + nt*8 + gg;
            int k0 = kt*8 + tt, k1 = k0 + 4;
            const float* zi = &Zi_s[col*25];
            float f0, f1;
            if (kt < 3){ f0 = zj[k0]*zi[k0]; f1 = zj[k1]*zi[k1]; }
            else { f0 = fabsf(zj[k0-24] - zi[k0-24]); f1 = fabsf(zj[k1-24] - zi[k1-24]); }
            uint2 u; u.x = f2tf32(f0); u.y = f2tf32(f1);
            dst[e] = u;
        }
    };

    build(0, 0);
    __syncthreads();

    const int ccol = w*16 + 2*t4;

    for (int jj = 0; jj < JT; jj++){
        const int p = jj & 1;
        if (jj + 1 < JT) build(jj + 1, p ^ 1);

        float cj[6][2];
        #pragma unroll
        for (int mt = 0; mt < 6; mt++){
            cj[mt][0] = Cj_s[p*96 + mt*16 + g];
            cj[mt][1] = Cj_s[p*96 + mt*16 + g + 8];
        }
        u32 bf[2][6][2];
        #pragma unroll
        for (int nt = 0; nt < 2; nt++)
            #pragma unroll
            for (int kt = 0; kt < 6; kt++){
                uint2 u = Bsw[p*3072 + ((kt*8 + w)*2 + nt)*32 + lane];
                bf[nt][kt][0] = u.x; bf[nt][kt][1] = u.y;
            }

        float pA[4] = {0.f, 0.f, 0.f, 0.f};
        #pragma unroll
        for (int mt = 0; mt < 6; mt++){
            uint4 af[6];
            #pragma unroll
            for (int kt = 0; kt < 6; kt++) af[kt] = Asw[(mt*6 + kt)*32 + lane];
            #pragma unroll
            for (int nt = 0; nt < 2; nt++){
                float d0 = 0.f, d1 = 0.f, d2 = 0.f, d3 = 0.f;
                #pragma unroll
                for (int kt = 0; kt < 6; kt++)
                    mma_tf32(d0, d1, d2, d3,
                             af[kt].x, af[kt].y, af[kt].z, af[kt].w,
                             bf[nt][kt][0], bf[nt][kt][1]);
                const int c = ccol + nt*8;
                const int h0 = mt*16 + g;
                float v0 = fmaxf(d0 + cj[mt][0] + Ci_s[c*100 + h0],        0.f);
                float v1 = fmaxf(d1 + cj[mt][0] + Ci_s[(c+1)*100 + h0],    0.f);
                float v2 = fmaxf(d2 + cj[mt][1] + Ci_s[c*100 + h0 + 8],    0.f);
                float v3 = fmaxf(d3 + cj[mt][1] + Ci_s[(c+1)*100 + h0 + 8],0.f);
                pA[nt*2]   = fmaf(ws[mt][0], v0, fmaf(ws[mt][1], v2, pA[nt*2]));
                pA[nt*2+1] = fmaf(ws[mt][0], v1, fmaf(ws[mt][1], v3, pA[nt*2+1]));
            }
        }
        #pragma unroll
        for (int q = 0; q < 4; q++){
            pA[q] += __shfl_xor_sync(0xffffffffu, pA[q], 4);
            pA[q] += __shfl_xor_sync(0xffffffffu, pA[q], 8);
            pA[q] += __shfl_xor_sync(0xffffffffu, pA[q], 16);
        }
        if (g == 0){
            float* dst = &g_P[(size_t)(base + j0 + jj)*Sn + i0 + w*16];
            *(float2*)(dst + 2*t4)     = make_float2(pA[0] + bs2v, pA[1] + bs2v);
            *(float2*)(dst + 8 + 2*t4) = make_float2(pA[2] + bs2v, pA[3] + bs2v);
        }
        __syncthreads();
    }
}

// =================== kernel 3: masked softmax over i (in place) ===================
__global__ __launch_bounds__(256) void k_softmax(const float* __restrict__ mask){
    const int r = blockIdx.x;
    const int b = r / Sn;
    float* row = g_P + (size_t)r*Sn;
    const float* mrow = mask + (size_t)b*Sn;
    const int t = threadIdx.x;
    __shared__ float red[256];

    float vals[4]; float mx = -3.402823466e38f;
    #pragma unroll
    for (int q = 0; q < 4; q++){
        int i = t + q*256;
        float v = row[i] + (1.0f - mrow[i]) * (-3.402823466e38f);
        vals[q] = v; mx = fmaxf(mx, v);
    }
    red[t] = mx; __syncthreads();
    for (int s = 128; s > 0; s >>= 1){ if (t < s) red[t] = fmaxf(red[t], red[t+s]); __syncthreads(); }
    mx = red[0]; __syncthreads();

    float sum = 0.f;
    #pragma unroll
    for (int q = 0; q < 4; q++){ vals[q] = __expf(vals[q] - mx); sum += vals[q]; }
    red[t] = sum; __syncthreads();
    for (int s = 128; s > 0; s >>= 1){ if (t < s) red[t] += red[t+s]; __syncthreads(); }
    float inv = 1.0f / red[0];
    #pragma unroll
    for (int q = 0; q < 4; q++) row[t + q*256] = vals[q] * inv;
}

// =================== balanced f32x2 GEMM ===================
// MODE 0: ctx partial = P[:, ks] @ Hi[ks, :]        (K=512, ks in {0,1}, per batch)
// MODE 1: h1 partial  (K=768 per slice, ks in {0,1,2}: ctx / Hj / ctx*Hj)
// MODE 2: out = alpha*( relu(h1A+h1B+h1C+bv1) @ Wv2^T + bv2 )  (K=768)
template<int MODE>
__global__ __launch_bounds__(128) void k_gemm(
    const float* __restrict__ BW,
    const float* __restrict__ Hj,
    const float* __restrict__ bias,    // MODE2: bv1
    const float* __restrict__ bias2,   // MODE2: bv2
    const float* __restrict__ alpha_p,
    float* __restrict__ Cout)
{
    constexpr int KH = (MODE == 0) ? 512 : 768;
    constexpr int T  = KH / 16;
    __shared__ __align__(16) float As[2][16][64];
    __shared__ __align__(16) float Bs[2][16][128];

    const int t  = threadIdx.x;
    const int n0 = blockIdx.x * 128;
    const int m0 = blockIdx.y * 64;
    int b = 0, ks = 0;
    if (MODE == 0){ b = blockIdx.z >> 1; ks = blockIdx.z & 1; }
    if (MODE == 1){ ks = blockIdx.z; }
    const int rowbase = (MODE == 0) ? b*Sn + m0 : m0;
    const int kbase   = ks * KH;

    const int am = t >> 1, ah8 = (t & 1) * 8;
    const int b0r = t >> 3, b0q = (t & 7);
    const int ty = t >> 4, tx = t & 15;
    const int swt = swzB(t & 127);

    const float* ArowP  = g_P    + (size_t)(rowbase + am)*Sn + kbase;
    const float* ArowCA = g_ctxA + (size_t)(rowbase + am)*Hn;
    const float* ArowCB = g_ctxB + (size_t)(rowbase + am)*Hn;
    const float* ArowH  = (MODE == 1) ? (Hj + (size_t)(rowbase + am)*Hn) : (const float*)0;
    const float* ArowA  = g_h1A  + (size_t)(rowbase + am)*Hn;
    const float* ArowB  = g_h1B  + (size_t)(rowbase + am)*Hn;
    const float* ArowC  = g_h1C  + (size_t)(rowbase + am)*Hn;
    const float* Bsrc   = (MODE == 0) ? (BW + (size_t)b*Sn*Hn) : BW;

    float4 ra0, ra1, rb0, rb1, rb2, rb3;

    auto ldg = [&](int kt){
        const int kb = kt * 16;
        if (MODE == 0){
            ra0 = *(const float4*)(ArowP + kb + ah8);
            ra1 = *(const float4*)(ArowP + kb + ah8 + 4);
        } else if (MODE == 2){
            const int fo = kb + ah8;
            float4 xa0 = *(const float4*)(ArowA + fo);
            float4 xa1 = *(const float4*)(ArowA + fo + 4);
            float4 xb0 = *(const float4*)(ArowB + fo);
            float4 xb1 = *(const float4*)(ArowB + fo + 4);
            float4 xc0 = *(const float4*)(ArowC + fo);
            float4 xc1 = *(const float4*)(ArowC + fo + 4);
            float4 bb0 = *(const float4*)(bias + fo);
            float4 bb1 = *(const float4*)(bias + fo + 4);
            ra0 = make_float4(fmaxf(xa0.x+xb0.x+xc0.x+bb0.x,0.f), fmaxf(xa0.y+xb0.y+xc0.y+bb0.y,0.f),
                              fmaxf(xa0.z+xb0.z+xc0.z+bb0.z,0.f), fmaxf(xa0.w+xb0.w+xc0.w+bb0.w,0.f));
            ra1 = make_float4(fmaxf(xa1.x+xb1.x+xc1.x+bb1.x,0.f), fmaxf(xa1.y+xb1.y+xc1.y+bb1.y,0.f),
                              fmaxf(xa1.z+xb1.z+xc1.z+bb1.z,0.f), fmaxf(xa1.w+xb1.w+xc1.w+bb1.w,0.f));
        } else { // MODE 1: slice by ks
            const int fo = kb + ah8;
            if (ks == 0){
                float4 c0 = *(const float4*)(ArowCA + fo);
                float4 c1 = *(const float4*)(ArowCA + fo + 4);
                float4 d0 = *(const float4*)(ArowCB + fo);
                float4 d1 = *(const float4*)(ArowCB + fo + 4);
                ra0 = make_float4(c0.x+d0.x, c0.y+d0.y, c0.z+d0.z, c0.w+d0.w);
                ra1 = make_float4(c1.x+d1.x, c1.y+d1.y, c1.z+d1.z, c1.w+d1.w);
            } else if (ks == 1){
                ra0 = *(const float4*)(ArowH + fo);
                ra1 = *(const float4*)(ArowH + fo + 4);
            } else {
                float4 c0 = *(const float4*)(ArowCA + fo);
                float4 c1 = *(const float4*)(ArowCA + fo + 4);
                float4 d0 = *(const float4*)(ArowCB + fo);
                float4 d1 = *(const float4*)(ArowCB + fo + 4);
                float4 h0 = *(const float4*)(ArowH + fo);
                float4 h1 = *(const float4*)(ArowH + fo + 4);
                ra0 = make_float4((c0.x+d0.x)*h0.x, (c0.y+d0.y)*h0.y,
                                  (c0.z+d0.z)*h0.z, (c0.w+d0.w)*h0.w);
                ra1 = make_float4((c1.x+d1.x)*h1.x, (c1.y+d1.y)*h1.y,
                                  (c1.z+d1.z)*h1.z, (c1.w+d1.w)*h1.w);
            }
        }
        if (MODE == 0){
            const float* s = Bsrc + (size_t)(kbase + kb + b0r)*Hn + n0 + b0q*16;
            rb0 = *(const float4*)s;       rb1 = *(const float4*)(s + 4);
            rb2 = *(const float4*)(s + 8); rb3 = *(const float4*)(s + 12);
        } else {
            constexpr int KW = (MODE == 1) ? 2304 : 768;
            const float* s = Bsrc + (size_t)(n0 + t)*KW + kbase + kb;
            rb0 = *(const float4*)s;       rb1 = *(const float4*)(s + 4);
            rb2 = *(const float4*)(s + 8); rb3 = *(const float4*)(s + 12);
        }
    };
    auto sts = [&](int buf){
        float* Af = &As[buf][0][0];
        Af[(ah8+0)*64 + am] = ra0.x; Af[(ah8+1)*64 + am] = ra0.y;
        Af[(ah8+2)*64 + am] = ra0.z; Af[(ah8+3)*64 + am] = ra0.w;
        Af[(ah8+4)*64 + am] = ra1.x; Af[(ah8+5)*64 + am] = ra1.y;
        Af[(ah8+6)*64 + am] = ra1.z; Af[(ah8+7)*64 + am] = ra1.w;
        if (MODE == 0){
            float* d = &Bs[buf][b0r][0];
            *(float4*)(d + 8*b0q)          = rb0;
            *(float4*)(d + 64 + 8*b0q)     = rb1;
            *(float4*)(d + 8*b0q + 4)      = rb2;
            *(float4*)(d + 64 + 8*b0q + 4) = rb3;
        } else {
            Bs[buf][ 0][swt] = rb0.x; Bs[buf][ 1][swt] = rb0.y;
            Bs[buf][ 2][swt] = rb0.z; Bs[buf][ 3][swt] = rb0.w;
            Bs[buf][ 4][swt] = rb1.x; Bs[buf][ 5][swt] = rb1.y;
            Bs[buf][ 6][swt] = rb1.z; Bs[buf][ 7][swt] = rb1.w;
            Bs[buf][ 8][swt] = rb2.x; Bs[buf][ 9][swt] = rb2.y;
            Bs[buf][10][swt] = rb2.z; Bs[buf][11][swt] = rb2.w;
            Bs[buf][12][swt] = rb3.x; Bs[buf][13][swt] = rb3.y;
            Bs[buf][14][swt] = rb3.z; Bs[buf][15][swt] = rb3.w;
        }
    };

    u64 acc[4][8];
    #pragma unroll
    for (int m = 0; m < 4; m++)
        #pragma unroll
        for (int n = 0; n < 8; n++) acc[m][n] = 0ull;

    ldg(0); sts(0); __syncthreads();

    for (int tt = 0; tt < T; tt++){
        const int cur = tt & 1;
        if (tt + 1 < T) ldg(tt + 1);
        #pragma unroll
        for (int k = 0; k < 16; k++){
            ulonglong2 A01 = *(const ulonglong2*)&As[cur][k][ty*8];
            ulonglong2 A23 = *(const ulonglong2*)&As[cur][k][ty*8 + 4];
            float4 bq0 = *(const float4*)&Bs[cur][k][tx*4];
            float4 bq1 = *(const float4*)&Bs[cur][k][64 + tx*4];
            u64 av[4] = {A01.x, A01.y, A23.x, A23.y};
            u64 bd[8] = {pack2(bq0.x,bq0.x), pack2(bq0.y,bq0.y),
                         pack2(bq0.z,bq0.z), pack2(bq0.w,bq0.w),
                         pack2(bq1.x,bq1.x), pack2(bq1.y,bq1.y),
                         pack2(bq1.z,bq1.z), pack2(bq1.w,bq1.w)};
            #pragma unroll
            for (int m = 0; m < 4; m++)
                #pragma unroll
                for (int n = 0; n < 8; n++)
                    acc[m][n] = fma2(av[m], bd[n], acc[m][n]);
        }
        if (tt + 1 < T) sts(cur ^ 1);
        __syncthreads();
    }

    const float alpha = (MODE == 2) ? alpha_p[0] : 1.0f;
    const int nbase = n0 + tx*8;
    float badd[8];
    if (MODE == 2){
        float4 v0 = *(const float4*)(bias2 + nbase);
        float4 v1 = *(const float4*)(bias2 + nbase + 4);
        badd[0]=v0.x; badd[1]=v0.y; badd[2]=v0.z; badd[3]=v0.w;
        badd[4]=v1.x; badd[5]=v1.y; badd[6]=v1.z; badd[7]=v1.w;
    }
    #pragma unroll
    for (int r = 0; r < 8; r++){
        const int mp = r >> 1, part = r & 1;
        float out[8];
        #pragma unroll
        for (int q = 0; q < 8; q++){
            float2 v = unpack2(acc[mp][q]);
            out[q] = part ? v.y : v.x;
        }
        if (MODE == 2){
            #pragma unroll
            for (int q = 0; q < 8; q++) out[q] = (out[q] + badd[q]) * alpha;
        }
        float* dst;
        const size_t roff = (size_t)(rowbase + ty*8 + r)*Hn + nbase;
        if      (MODE == 0) dst = (ks == 0 ? g_ctxA : g_ctxB) + roff;
        else if (MODE == 1) dst = (ks == 0 ? g_h1A : (ks == 1 ? g_h1B : g_h1C)) + roff;
        else                dst = Cout + roff;
        *(float4*)dst       = *(float4*)&out[0];
        *(float4*)(dst + 4) = *(float4*)&out[4];
    }
}

// =============================== launch ===============================
extern "C" void kernel_launch(void* const* d_in, const int* in_sizes, int n_in,
                              void* d_out, int out_size)
{
    const float* Hj    = (const float*)d_in[0];
    const float* Hi    = (const float*)d_in[1];
    const float* mask  = (const float*)d_in[2];
    const float* Wpj   = (const float*)d_in[3];
    const float* Wpi   = (const float*)d_in[4];
    const float* Ws1   = (const float*)d_in[5];
    const float* bs1   = (const float*)d_in[6];
    const float* Ws2   = (const float*)d_in[7];
    const float* bs2   = (const float*)d_in[8];
    const float* Wv1   = (const float*)d_in[9];
    const float* bv1   = (const float*)d_in[10];
    const float* Wv2   = (const float*)d_in[11];
    const float* bv2   = (const float*)d_in[12];
    const float* alpha = (const float*)d_in[13];
    float* out = (float*)d_out;

    cudaFuncSetAttribute(k_pair_mma, cudaFuncAttributeMaxDynamicSharedMemorySize, SMEM_PAIR);

    k_proj<<<Bn*Sn, 256>>>(Hj, Hi, Wpj, Wpi, Ws1, bs1);

    dim3 gp(Sn/IT, Sn/JT, Bn);
    k_pair_mma<<<gp, 256, SMEM_PAIR>>>(Ws1, Ws2, bs2);

    k_softmax<<<Bn*Sn, 256>>>(mask);

    dim3 g0(Hn/128, Sn/64, Bn*2);
    k_gemm<0><<<g0, 128>>>(Hi, nullptr, nullptr, nullptr, nullptr, nullptr);

    dim3 g1(Hn/128, (Bn*Sn)/64, 3);
    k_gemm<1><<<g1, 128>>>(Wv1, Hj, nullptr, nullptr, nullptr, nullptr);

    dim3 g2(Hn/128, (Bn*Sn)/64, 1);
    k_gemm<2><<<g2, 128>>>(Wv2, nullptr, bv1, bv2, alpha, out);
}

// round 12
// speedup vs baseline: 1.1345x; 1.1054x over previous
#include <cuda_runtime.h>
#include <cuda_bf16.h>

typedef unsigned long long u64;
typedef unsigned int u32;

#define Bn   2
#define Sn   1024
#define Hn   768
#define Dn   24
#define HIDn 96

// ---------------- scratch ----------------
__device__ float g_Zj  [Bn*Sn*Dn];
__device__ float g_Zi  [Bn*Sn*Dn];
__device__ float g_Cj  [Bn*Sn*HIDn];   // Ws1[:,0:24]@Zj + b1  (b1 folded here)
__device__ float g_P   [Bn*Sn*Sn];
__device__ float g_ctxA[Bn*Sn*Hn];
__device__ float g_ctxB[Bn*Sn*Hn];
__device__ float g_h1A [Bn*Sn*Hn];
__device__ float g_h1B [Bn*Sn*Hn];

// ---------------- packed f32x2 helpers ----------------
__device__ __forceinline__ u64 pack2(float x, float y){
    u64 r;
    asm("mov.b64 %0, {%1, %2};" : "=l"(r)
        : "r"(__float_as_uint(x)), "r"(__float_as_uint(y)));
    return r;
}
__device__ __forceinline__ float2 unpack2(u64 v){
    unsigned lo, hi;
    asm("mov.b64 {%0, %1}, %2;" : "=r"(lo), "=r"(hi) : "l"(v));
    return make_float2(__uint_as_float(lo), __uint_as_float(hi));
}
__device__ __forceinline__ u64 fma2(u64 a, u64 b, u64 c){
    u64 d;
    asm("fma.rn.f32x2 %0, %1, %2, %3;" : "=l"(d) : "l"(a), "l"(b), "l"(c));
    return d;
}
__device__ __forceinline__ int swzB(int n){
    return ((n >> 2) & 1) * 64 + ((n >> 3) << 2) + (n & 3);
}
__device__ __forceinline__ u32 f2tf32(float f){
    u32 r;
    asm("cvt.rna.tf32.f32 %0, %1;" : "=r"(r) : "f"(f));
    return r;
}
__device__ __forceinline__ void mma_tf32(
    float& d0, float& d1, float& d2, float& d3,
    u32 a0, u32 a1, u32 a2, u32 a3, u32 b0, u32 b1)
{
    asm("mma.sync.aligned.m16n8k8.row.col.f32.tf32.tf32.f32 "
        "{%0,%1,%2,%3},{%4,%5,%6,%7},{%8,%9},{%0,%1,%2,%3};"
        : "+f"(d0), "+f"(d1), "+f"(d2), "+f"(d3)
        : "r"(a0), "r"(a1), "r"(a2), "r"(a3), "r"(b0), "r"(b1));
}

// =================== kernel 1: projections + per-j MLP term ===================
__global__ __launch_bounds__(256) void k_proj(
    const float* __restrict__ Hj, const float* __restrict__ Hi,
    const float* __restrict__ Wpj, const float* __restrict__ Wpi,
    const float* __restrict__ Ws1, const float* __restrict__ bs1)
{
    __shared__ float shj[Hn], shi[Hn];
    __shared__ float sz[48];
    __shared__ float sws1[96][25];   // only cols 0:24 needed here
    const int row = blockIdx.x;
    const int t = threadIdx.x;
    const float* hj = Hj + (size_t)row*Hn;
    const float* hi = Hi + (size_t)row*Hn;
    for (int k = t; k < Hn; k += 256){ shj[k] = hj[k]; shi[k] = hi[k]; }
    for (int idx = t; idx < 96*24; idx += 256) sws1[idx/24][idx%24] = Ws1[(idx/24)*96 + (idx%24)];
    __syncthreads();

    const int w = t >> 5, lane = t & 31;
    for (int o = w; o < 48; o += 8){
        const float* wv = (o < 24) ? (Wpj + (size_t)o*Hn) : (Wpi + (size_t)(o-24)*Hn);
        const float* x  = (o < 24) ? shj : shi;
        float s0 = 0.f, s1 = 0.f;
        #pragma unroll
        for (int h = lane; h < Hn; h += 64){
            s0 = fmaf(wv[h],    x[h],    s0);
            s1 = fmaf(wv[h+32], x[h+32], s1);
        }
        float s = s0 + s1;
        #pragma unroll
        for (int off = 16; off; off >>= 1) s += __shfl_xor_sync(0xffffffffu, s, off);
        if (lane == 0){
            sz[o] = s;
            if (o < 24) g_Zj[(size_t)row*24 + o]      = s;
            else        g_Zi[(size_t)row*24 + (o-24)] = s;
        }
    }
    __syncthreads();

    if (t < 96){
        float s = bs1[t];
        #pragma unroll
        for (int d = 0; d < 24; d++) s = fmaf(sws1[t][d], sz[d], s);
        g_Cj[(size_t)row*96 + t] = s;
    }
}

// =================== kernel 2: pair MLP via tf32 mma, K=72 (dyn48 + Zi24) ===================
// JT=64, IT=128 -> grid 256 CTAs, ~83KB smem -> 2 CTAs/SM.
// logits = bs2 + sum_h ws2[h]*relu( (W1[:, perm]@[had;abs;Zi])[h,i] + Cj'[j,h] )
#define JT 64
#define IT 128

#define OFF_ASW  0                           // 6mt*9kt*32 uint4 = 27648
#define OFF_BDYN 27648                       // 6kt*8w*2nt*32 uint2 = 24576
#define OFF_BZI  (27648+24576)               // 3kt*... = 12288
#define OFF_ZI   (OFF_BZI+12288)             // 128*25 f = 12800
#define OFF_ZJ   (OFF_ZI+12800)              // 64*25 f = 6400
#define OFF_CJ   (OFF_ZJ+6400)               // 96 f = 384
#define OFF_WS2  (OFF_CJ+384)                // 96 f = 384
#define SMEM_PAIR (OFF_WS2+384)              // ~84.5KB

__global__ __launch_bounds__(256, 2) void k_pair_mma(
    const float* __restrict__ Ws1, const float* __restrict__ Ws2,
    const float* __restrict__ bs2)
{
    extern __shared__ __align__(16) char smem[];
    uint4* Asw  = (uint4*)(smem + OFF_ASW);
    uint2* Bdyn = (uint2*)(smem + OFF_BDYN);
    uint2* Bzi  = (uint2*)(smem + OFF_BZI);
    float* Zi_s = (float*)(smem + OFF_ZI);
    float* Zj_s = (float*)(smem + OFF_ZJ);
    float* Cj_s = (float*)(smem + OFF_CJ);
    float* ws2s = (float*)(smem + OFF_WS2);

    const int t  = threadIdx.x;
    const int i0 = blockIdx.x * IT;
    const int j0 = blockIdx.y * JT;
    const int b  = blockIdx.z;
    const int base = b * Sn;
    const int w = t >> 5, lane = t & 31;
    const int g = lane >> 2, t4 = lane & 3;

    // A fragments: W1 permuted cols, tf32. col(k) = k<48 ? 48+k : k-24
    for (int idx = t; idx < 1728; idx += 256){
        int mt = idx / 288, r = idx % 288, kt = r / 32, ln = r % 32;
        int gg = ln >> 2, tt = ln & 3;
        int h = mt*16 + gg;
        int k0 = kt*8 + tt, k1 = k0 + 4;
        int c0 = (k0 < 48) ? 48 + k0 : k0 - 24;
        int c1 = (k1 < 48) ? 48 + k1 : k1 - 24;
        uint4 v;
        v.x = f2tf32(Ws1[h*96 + c0]);
        v.y = f2tf32(Ws1[(h+8)*96 + c0]);
        v.z = f2tf32(Ws1[h*96 + c1]);
        v.w = f2tf32(Ws1[(h+8)*96 + c1]);
        Asw[idx] = v;
    }
    for (int idx = t; idx < IT*24; idx += 256){
        int r = idx / 24, k = idx % 24;
        Zi_s[r*25 + k] = g_Zi[(size_t)(base + i0 + r)*24 + k];
    }
    for (int idx = t; idx < JT*24; idx += 256){
        int r = idx / 24, k = idx % 24;
        Zj_s[r*25 + k] = g_Zj[(size_t)(base + j0 + r)*24 + k];
    }
    if (t < 96) ws2s[t] = Ws2[t];
    const float bs2v = bs2[0];
    __syncthreads();

    // static Zi B fragments (kt 6..8): F[k-48, col] = Zi[col, k-48]
    for (int e = t; e < 1536; e += 256){
        int ktl = e >> 9, ww = (e >> 6) & 7, nt = (e >> 5) & 1, ln = e & 31;
        int gg = ln >> 2, tt = ln & 3;
        int col = ww*16 + nt*8 + gg;
        int k0 = ktl*8 + tt, k1 = k0 + 4;
        uint2 u;
        u.x = f2tf32(Zi_s[col*25 + k0]);
        u.y = f2tf32(Zi_s[col*25 + k1]);
        Bzi[e] = u;
    }

    for (int jj = 0; jj < JT; jj++){
        __syncthreads();   // prev compute done reading Bdyn/Cj_s (also covers Bzi init)
        // build dyn features for this j
        if (t < 96) Cj_s[t] = g_Cj[(size_t)(base + j0 + jj)*96 + t];
        {
            const float* zj = &Zj_s[jj*25];
            #pragma unroll
            for (int q = 0; q < 12; q++){
                int e = t + q*256;
                int kt = e >> 9, ww = (e >> 6) & 7, nt = (e >> 5) & 1, ln = e & 31;
                int gg = ln >> 2, tt = ln & 3;
                int col = ww*16 + nt*8 + gg;
                int k0 = kt*8 + tt, k1 = k0 + 4;
                const float* zi = &Zi_s[col*25];
                float f0, f1;
                if (kt < 3){ f0 = zj[k0]*zi[k0]; f1 = zj[k1]*zi[k1]; }
                else { f0 = fabsf(zj[k0-24] - zi[k0-24]); f1 = fabsf(zj[k1-24] - zi[k1-24]); }
                uint2 u; u.x = f2tf32(f0); u.y = f2tf32(f1);
                Bdyn[e] = u;
            }
        }
        __syncthreads();

        // B fragments for this warp's 16 cols (9 kt)
        u32 bf[2][9][2];
        #pragma unroll
        for (int nt = 0; nt < 2; nt++){
            #pragma unroll
            for (int kt = 0; kt < 6; kt++){
                uint2 u = Bdyn[((kt*8 + w)*2 + nt)*32 + lane];
                bf[nt][kt][0] = u.x; bf[nt][kt][1] = u.y;
            }
            #pragma unroll
            for (int kt = 6; kt < 9; kt++){
                uint2 u = Bzi[(((kt-6)*8 + w)*2 + nt)*32 + lane];
                bf[nt][kt][0] = u.x; bf[nt][kt][1] = u.y;
            }
        }

        float pA[4] = {0.f, 0.f, 0.f, 0.f};
        #pragma unroll
        for (int mt = 0; mt < 6; mt++){
            uint4 af[9];
            #pragma unroll
            for (int kt = 0; kt < 9; kt++) af[kt] = Asw[(mt*9 + kt)*32 + lane];
            const float wsa = ws2s[mt*16 + g],  wsb = ws2s[mt*16 + g + 8];
            const float cja = Cj_s[mt*16 + g],  cjb = Cj_s[mt*16 + g + 8];
            #pragma unroll
            for (int nt = 0; nt < 2; nt++){
                float d0 = 0.f, d1 = 0.f, d2 = 0.f, d3 = 0.f;
                #pragma unroll
                for (int kt = 0; kt < 9; kt++)
                    mma_tf32(d0, d1, d2, d3,
                             af[kt].x, af[kt].y, af[kt].z, af[kt].w,
                             bf[nt][kt][0], bf[nt][kt][1]);
                float v0 = fmaxf(d0 + cja, 0.f);
                float v1 = fmaxf(d1 + cja, 0.f);
                float v2 = fmaxf(d2 + cjb, 0.f);
                float v3 = fmaxf(d3 + cjb, 0.f);
                pA[nt*2]   = fmaf(wsa, v0, fmaf(wsb, v2, pA[nt*2]));
                pA[nt*2+1] = fmaf(wsa, v1, fmaf(wsb, v3, pA[nt*2+1]));
            }
        }
        #pragma unroll
        for (int q = 0; q < 4; q++){
            pA[q] += __shfl_xor_sync(0xffffffffu, pA[q], 4);
            pA[q] += __shfl_xor_sync(0xffffffffu, pA[q], 8);
            pA[q] += __shfl_xor_sync(0xffffffffu, pA[q], 16);
        }
        if (g == 0){
            float* dst = &g_P[(size_t)(base + j0 + jj)*Sn + i0 + w*16];
            *(float2*)(dst + 2*t4)     = make_float2(pA[0] + bs2v, pA[1] + bs2v);
            *(float2*)(dst + 8 + 2*t4) = make_float2(pA[2] + bs2v, pA[3] + bs2v);
        }
    }
}

// =================== kernel 3: masked softmax over i (in place) ===================
__global__ __launch_bounds__(256) void k_softmax(const float* __restrict__ mask){
    const int r = blockIdx.x;
    const int b = r / Sn;
    float* row = g_P + (size_t)r*Sn;
    const float* mrow = mask + (size_t)b*Sn;
    const int t = threadIdx.x;
    __shared__ float red[256];

    float vals[4]; float mx = -3.402823466e38f;
    #pragma unroll
    for (int q = 0; q < 4; q++){
        int i = t + q*256;
        float v = row[i] + (1.0f - mrow[i]) * (-3.402823466e38f);
        vals[q] = v; mx = fmaxf(mx, v);
    }
    red[t] = mx; __syncthreads();
    for (int s = 128; s > 0; s >>= 1){ if (t < s) red[t] = fmaxf(red[t], red[t+s]); __syncthreads(); }
    mx = red[0]; __syncthreads();

    float sum = 0.f;
    #pragma unroll
    for (int q = 0; q < 4; q++){ vals[q] = __expf(vals[q] - mx); sum += vals[q]; }
    red[t] = sum; __syncthreads();
    for (int s = 128; s > 0; s >>= 1){ if (t < s) red[t] += red[t+s]; __syncthreads(); }
    float inv = 1.0f / red[0];
    #pragma unroll
    for (int q = 0; q < 4; q++) row[t + q*256] = vals[q] * inv;
}

// =================== balanced f32x2 GEMM (R7 version: 2-way splits) ===================
// MODE 0: ctx partial = P[:, ks] @ Hi[ks, :]            (K=512 per half)
// MODE 1: h1 partial  = feat[:, ks] @ Wv1[:, ks]^T      (K=1152 per half)
// MODE 2: out = alpha*( relu(h1A+h1B+bv1) @ Wv2^T + bv2 )  (K=768)
template<int MODE>
__global__ __launch_bounds__(128) void k_gemm(
    const float* __restrict__ BW,
    const float* __restrict__ Hj,
    const float* __restrict__ bias,    // MODE2: bv1
    const float* __restrict__ bias2,   // MODE2: bv2
    const float* __restrict__ alpha_p,
    float* __restrict__ Cout)
{
    constexpr int KH = (MODE == 0) ? 512 : (MODE == 1) ? 1152 : 768;
    constexpr int T  = KH / 16;
    __shared__ __align__(16) float As[2][16][64];
    __shared__ __align__(16) float Bs[2][16][128];

    const int t  = threadIdx.x;
    const int n0 = blockIdx.x * 128;
    const int m0 = blockIdx.y * 64;
    int b = 0, ks = 0;
    if (MODE == 0){ b = blockIdx.z >> 1; ks = blockIdx.z & 1; }
    if (MODE == 1){ ks = blockIdx.z; }
    const int rowbase = (MODE == 0) ? b*Sn + m0 : m0;
    const int kbase   = ks * KH;

    const int am = t >> 1, ah8 = (t & 1) * 8;
    const int b0r = t >> 3, b0q = (t & 7);
    const int ty = t >> 4, tx = t & 15;
    const int swt = swzB(t & 127);

    const float* ArowP  = g_P    + (size_t)(rowbase + am)*Sn + kbase;
    const float* ArowCA = g_ctxA + (size_t)(rowbase + am)*Hn;
    const float* ArowCB = g_ctxB + (size_t)(rowbase + am)*Hn;
    const float* ArowH  = (MODE == 1) ? (Hj + (size_t)(rowbase + am)*Hn) : (const float*)0;
    const float* ArowA  = g_h1A  + (size_t)(rowbase + am)*Hn;
    const float* ArowB  = g_h1B  + (size_t)(rowbase + am)*Hn;
    const float* Bsrc   = (MODE == 0) ? (BW + (size_t)b*Sn*Hn) : BW;

    float4 ra0, ra1, rb0, rb1, rb2, rb3;

    auto ldg = [&](int kt){
        const int kb = kt * 16;
        if (MODE == 0){
            ra0 = *(const float4*)(ArowP + kb + ah8);
            ra1 = *(const float4*)(ArowP + kb + ah8 + 4);
        } else if (MODE == 2){
            const int fo = kb + ah8;
            float4 xa0 = *(const float4*)(ArowA + fo);
            float4 xa1 = *(const float4*)(ArowA + fo + 4);
            float4 xb0 = *(const float4*)(ArowB + fo);
            float4 xb1 = *(const float4*)(ArowB + fo + 4);
            float4 bb0 = *(const float4*)(bias + fo);
            float4 bb1 = *(const float4*)(bias + fo + 4);
            ra0 = make_float4(fmaxf(xa0.x+xb0.x+bb0.x,0.f), fmaxf(xa0.y+xb0.y+bb0.y,0.f),
                              fmaxf(xa0.z+xb0.z+bb0.z,0.f), fmaxf(xa0.w+xb0.w+bb0.w,0.f));
            ra1 = make_float4(fmaxf(xa1.x+xb1.x+bb1.x,0.f), fmaxf(xa1.y+xb1.y+bb1.y,0.f),
                              fmaxf(xa1.z+xb1.z+bb1.z,0.f), fmaxf(xa1.w+xb1.w+bb1.w,0.f));
        } else {
            const int fo = kbase + kb + ah8;
            if (fo < 768){
                float4 c0 = *(const float4*)(ArowCA + fo);
                float4 c1 = *(const float4*)(ArowCA + fo + 4);
                float4 d0 = *(const float4*)(ArowCB + fo);
                float4 d1 = *(const float4*)(ArowCB + fo + 4);
                ra0 = make_float4(c0.x+d0.x, c0.y+d0.y, c0.z+d0.z, c0.w+d0.w);
                ra1 = make_float4(c1.x+d1.x, c1.y+d1.y, c1.z+d1.z, c1.w+d1.w);
            } else if (fo < 1536){
                ra0 = *(const float4*)(ArowH + fo - 768);
                ra1 = *(const float4*)(ArowH + fo - 764);
            } else {
                const int go = fo - 1536;
                float4 c0 = *(const float4*)(ArowCA + go);
                float4 c1 = *(const float4*)(ArowCA + go + 4);
                float4 d0 = *(const float4*)(ArowCB + go);
                float4 d1 = *(const float4*)(ArowCB + go + 4);
                float4 h0 = *(const float4*)(ArowH + go);
                float4 h1 = *(const float4*)(ArowH + go + 4);
                ra0 = make_float4((c0.x+d0.x)*h0.x, (c0.y+d0.y)*h0.y,
                                  (c0.z+d0.z)*h0.z, (c0.w+d0.w)*h0.w);
                ra1 = make_float4((c1.x+d1.x)*h1.x, (c1.y+d1.y)*h1.y,
                                  (c1.z+d1.z)*h1.z, (c1.w+d1.w)*h1.w);
            }
        }
        if (MODE == 0){
            const float* s = Bsrc + (size_t)(kbase + kb + b0r)*Hn + n0 + b0q*16;
            rb0 = *(const float4*)s;       rb1 = *(const float4*)(s + 4);
            rb2 = *(const float4*)(s + 8); rb3 = *(const float4*)(s + 12);
        } else {
            constexpr int KW = (MODE == 1) ? 2304 : 768;
            const float* s = Bsrc + (size_t)(n0 + t)*KW + kbase + kb;
            rb0 = *(const float4*)s;       rb1 = *(const float4*)(s + 4);
            rb2 = *(const float4*)(s + 8); rb3 = *(const float4*)(s + 12);
        }
    };
    auto sts = [&](int buf){
        float* Af = &As[buf][0][0];
        Af[(ah8+0)*64 + am] = ra0.x; Af[(ah8+1)*64 + am] = ra0.y;
        Af[(ah8+2)*64 + am] = ra0.z; Af[(ah8+3)*64 + am] = ra0.w;
        Af[(ah8+4)*64 + am] = ra1.x; Af[(ah8+5)*64 + am] = ra1.y;
        Af[(ah8+6)*64 + am] = ra1.z; Af[(ah8+7)*64 + am] = ra1.w;
        if (MODE == 0){
            float* d = &Bs[buf][b0r][0];
            *(float4*)(d + 8*b0q)          = rb0;
            *(float4*)(d + 64 + 8*b0q)     = rb1;
            *(float4*)(d + 8*b0q + 4)      = rb2;
            *(float4*)(d + 64 + 8*b0q + 4) = rb3;
        } else {
            Bs[buf][ 0][swt] = rb0.x; Bs[buf][ 1][swt] = rb0.y;
            Bs[buf][ 2][swt] = rb0.z; Bs[buf][ 3][swt] = rb0.w;
            Bs[buf][ 4][swt] = rb1.x; Bs[buf][ 5][swt] = rb1.y;
            Bs[buf][ 6][swt] = rb1.z; Bs[buf][ 7][swt] = rb1.w;
            Bs[buf][ 8][swt] = rb2.x; Bs[buf][ 9][swt] = rb2.y;
            Bs[buf][10][swt] = rb2.z; Bs[buf][11][swt] = rb2.w;
            Bs[buf][12][swt] = rb3.x; Bs[buf][13][swt] = rb3.y;
            Bs[buf][14][swt] = rb3.z; Bs[buf][15][swt] = rb3.w;
        }
    };

    u64 acc[4][8];
    #pragma unroll
    for (int m = 0; m < 4; m++)
        #pragma unroll
        for (int n = 0; n < 8; n++) acc[m][n] = 0ull;

    ldg(0); sts(0); __syncthreads();

    for (int tt = 0; tt < T; tt++){
        const int cur = tt & 1;
        if (tt + 1 < T) ldg(tt + 1);
        #pragma unroll
        for (int k = 0; k < 16; k++){
            ulonglong2 A01 = *(const ulonglong2*)&As[cur][k][ty*8];
            ulonglong2 A23 = *(const ulonglong2*)&As[cur][k][ty*8 + 4];
            float4 bq0 = *(const float4*)&Bs[cur][k][tx*4];
            float4 bq1 = *(const float4*)&Bs[cur][k][64 + tx*4];
            u64 av[4] = {A01.x, A01.y, A23.x, A23.y};
            u64 bd[8] = {pack2(bq0.x,bq0.x), pack2(bq0.y,bq0.y),
                         pack2(bq0.z,bq0.z), pack2(bq0.w,bq0.w),
                         pack2(bq1.x,bq1.x), pack2(bq1.y,bq1.y),
                         pack2(bq1.z,bq1.z), pack2(bq1.w,bq1.w)};
            #pragma unroll
            for (int m = 0; m < 4; m++)
                #pragma unroll
                for (int n = 0; n < 8; n++)
                    acc[m][n] = fma2(av[m], bd[n], acc[m][n]);
        }
        if (tt + 1 < T) sts(cur ^ 1);
        __syncthreads();
    }

    const float alpha = (MODE == 2) ? alpha_p[0] : 1.0f;
    const int nbase = n0 + tx*8;
    float badd[8];
    if (MODE == 2){
        float4 v0 = *(const float4*)(bias2 + nbase);
        float4 v1 = *(const float4*)(bias2 + nbase + 4);
        badd[0]=v0.x; badd[1]=v0.y; badd[2]=v0.z; badd[3]=v0.w;
        badd[4]=v1.x; badd[5]=v1.y; badd[6]=v1.z; badd[7]=v1.w;
    }
    #pragma unroll
    for (int r = 0; r < 8; r++){
        const int mp = r >> 1, part = r & 1;
        float out[8];
        #pragma unroll
        for (int q = 0; q < 8; q++){
            float2 v = unpack2(acc[mp][q]);
            out[q] = part ? v.y : v.x;
        }
        if (MODE == 2){
            #pragma unroll
            for (int q = 0; q < 8; q++) out[q] = (out[q] + badd[q]) * alpha;
        }
        float* dst;
        const size_t roff = (size_t)(rowbase + ty*8 + r)*Hn + nbase;
        if      (MODE == 0) dst = (ks == 0 ? g_ctxA : g_ctxB) + roff;
        else if (MODE == 1) dst = (ks == 0 ? g_h1A  : g_h1B ) + roff;
        else                dst = Cout + roff;
        *(float4*)dst       = *(float4*)&out[0];
        *(float4*)(dst + 4) = *(float4*)&out[4];
    }
}

// =============================== launch ===============================
extern "C" void kernel_launch(void* const* d_in, const int* in_sizes, int n_in,
                              void* d_out, int out_size)
{
    const float* Hj    = (const float*)d_in[0];
    const float* Hi    = (const float*)d_in[1];
    const float* mask  = (const float*)d_in[2];
    const float* Wpj   = (const float*)d_in[3];
    const float* Wpi   = (const float*)d_in[4];
    const float* Ws1   = (const float*)d_in[5];
    const float* bs1   = (const float*)d_in[6];
    const float* Ws2   = (const float*)d_in[7];
    const float* bs2   = (const float*)d_in[8];
    const float* Wv1   = (const float*)d_in[9];
    const float* bv1   = (const float*)d_in[10];
    const float* Wv2   = (const float*)d_in[11];
    const float* bv2   = (const float*)d_in[12];
    const float* alpha = (const float*)d_in[13];
    float* out = (float*)d_out;

    cudaFuncSetAttribute(k_pair_mma, cudaFuncAttributeMaxDynamicSharedMemorySize, SMEM_PAIR);

    k_proj<<<Bn*Sn, 256>>>(Hj, Hi, Wpj, Wpi, Ws1, bs1);

    dim3 gp(Sn/IT, Sn/JT, Bn);
    k_pair_mma<<<gp, 256, SMEM_PAIR>>>(Ws1, Ws2, bs2);

    k_softmax<<<Bn*Sn, 256>>>(mask);

    dim3 g0(Hn/128, Sn/64, Bn*2);
    k_gemm<0><<<g0, 128>>>(Hi, nullptr, nullptr, nullptr, nullptr, nullptr);

    dim3 g1(Hn/128, (Bn*Sn)/64, 2);
    k_gemm<1><<<g1, 128>>>(Wv1, Hj, nullptr, nullptr, nullptr, nullptr);

    dim3 g2(Hn/128, (Bn*Sn)/64, 1);
    k_gemm<2><<<g2, 128>>>(Wv2, nullptr, bv1, bv2, alpha, out);
}

// round 13
// speedup vs baseline: 1.3298x; 1.1721x over previous
#include <cuda_runtime.h>
#include <cuda_bf16.h>

typedef unsigned long long u64;
typedef unsigned int u32;

#define Bn   2
#define Sn   1024
#define Hn   768
#define Dn   24
#define HIDn 96

// ---------------- scratch ----------------
__device__ float g_Zj  [Bn*Sn*Dn];
__device__ float g_Zi  [Bn*Sn*Dn];
__device__ float g_Cj  [Bn*Sn*HIDn];   // Ws1[:,0:24]@Zj + b1
__device__ float g_P   [Bn*Sn*Sn];
__device__ float g_ctxA[Bn*Sn*Hn];
__device__ float g_ctxB[Bn*Sn*Hn];
__device__ float g_h1A [Bn*Sn*Hn];
__device__ float g_h1B [Bn*Sn*Hn];

// ---------------- helpers ----------------
__device__ __forceinline__ u32 f2tf32(float f){
    u32 r;
    asm("cvt.rna.tf32.f32 %0, %1;" : "=r"(r) : "f"(f));
    return r;
}
__device__ __forceinline__ void mma_tf32(
    float& d0, float& d1, float& d2, float& d3,
    u32 a0, u32 a1, u32 a2, u32 a3, u32 b0, u32 b1)
{
    asm("mma.sync.aligned.m16n8k8.row.col.f32.tf32.tf32.f32 "
        "{%0,%1,%2,%3},{%4,%5,%6,%7},{%8,%9},{%0,%1,%2,%3};"
        : "+f"(d0), "+f"(d1), "+f"(d2), "+f"(d3)
        : "r"(a0), "r"(a1), "r"(a2), "r"(a3), "r"(b0), "r"(b1));
}

// =================== kernel 1: projections + per-j MLP term (R11) ===================
__global__ __launch_bounds__(256) void k_proj(
    const float* __restrict__ Hj, const float* __restrict__ Hi,
    const float* __restrict__ Wpj, const float* __restrict__ Wpi,
    const float* __restrict__ Ws1, const float* __restrict__ bs1)
{
    __shared__ float shj[Hn], shi[Hn];
    __shared__ float sz[48];
    __shared__ float sws1[96][25];
    const int row = blockIdx.x;
    const int t = threadIdx.x;
    const float* hj = Hj + (size_t)row*Hn;
    const float* hi = Hi + (size_t)row*Hn;
    for (int k = t; k < Hn; k += 256){ shj[k] = hj[k]; shi[k] = hi[k]; }
    for (int idx = t; idx < 96*24; idx += 256) sws1[idx/24][idx%24] = Ws1[(idx/24)*96 + (idx%24)];
    __syncthreads();

    const int w = t >> 5, lane = t & 31;
    for (int o = w; o < 48; o += 8){
        const float* wv = (o < 24) ? (Wpj + (size_t)o*Hn) : (Wpi + (size_t)(o-24)*Hn);
        const float* x  = (o < 24) ? shj : shi;
        float s0 = 0.f, s1 = 0.f;
        #pragma unroll
        for (int h = lane; h < Hn; h += 64){
            s0 = fmaf(wv[h],    x[h],    s0);
            s1 = fmaf(wv[h+32], x[h+32], s1);
        }
        float s = s0 + s1;
        #pragma unroll
        for (int off = 16; off; off >>= 1) s += __shfl_xor_sync(0xffffffffu, s, off);
        if (lane == 0){
            sz[o] = s;
            if (o < 24) g_Zj[(size_t)row*24 + o]      = s;
            else        g_Zi[(size_t)row*24 + (o-24)] = s;
        }
    }
    __syncthreads();

    if (t < 96){
        float s = bs1[t];
        #pragma unroll
        for (int d = 0; d < 24; d++) s = fmaf(sws1[t][d], sz[d], s);
        g_Cj[(size_t)row*96 + t] = s;
    }
}

// =================== kernel 2: pair MLP via tf32 mma, K=72 (R11, unchanged) ===================
#define JT 64
#define IT 128

#define OFF_ASW  0
#define OFF_BDYN 27648
#define OFF_BZI  (27648+24576)
#define OFF_ZI   (OFF_BZI+12288)
#define OFF_ZJ   (OFF_ZI+12800)
#define OFF_CJ   (OFF_ZJ+6400)
#define OFF_WS2  (OFF_CJ+384)
#define SMEM_PAIR (OFF_WS2+384)

__global__ __launch_bounds__(256, 2) void k_pair_mma(
    const float* __restrict__ Ws1, const float* __restrict__ Ws2,
    const float* __restrict__ bs2)
{
    extern __shared__ __align__(16) char smem[];
    uint4* Asw  = (uint4*)(smem + OFF_ASW);
    uint2* Bdyn = (uint2*)(smem + OFF_BDYN);
    uint2* Bzi  = (uint2*)(smem + OFF_BZI);
    float* Zi_s = (float*)(smem + OFF_ZI);
    float* Zj_s = (float*)(smem + OFF_ZJ);
    float* Cj_s = (float*)(smem + OFF_CJ);
    float* ws2s = (float*)(smem + OFF_WS2);

    const int t  = threadIdx.x;
    const int i0 = blockIdx.x * IT;
    const int j0 = blockIdx.y * JT;
    const int b  = blockIdx.z;
    const int base = b * Sn;
    const int w = t >> 5, lane = t & 31;
    const int g = lane >> 2, t4 = lane & 3;

    for (int idx = t; idx < 1728; idx += 256){
        int mt = idx / 288, r = idx % 288, kt = r / 32, ln = r % 32;
        int gg = ln >> 2, tt = ln & 3;
        int h = mt*16 + gg;
        int k0 = kt*8 + tt, k1 = k0 + 4;
        int c0 = (k0 < 48) ? 48 + k0 : k0 - 24;
        int c1 = (k1 < 48) ? 48 + k1 : k1 - 24;
        uint4 v;
        v.x = f2tf32(Ws1[h*96 + c0]);
        v.y = f2tf32(Ws1[(h+8)*96 + c0]);
        v.z = f2tf32(Ws1[h*96 + c1]);
        v.w = f2tf32(Ws1[(h+8)*96 + c1]);
        Asw[idx] = v;
    }
    for (int idx = t; idx < IT*24; idx += 256){
        int r = idx / 24, k = idx % 24;
        Zi_s[r*25 + k] = g_Zi[(size_t)(base + i0 + r)*24 + k];
    }
    for (int idx = t; idx < JT*24; idx += 256){
        int r = idx / 24, k = idx % 24;
        Zj_s[r*25 + k] = g_Zj[(size_t)(base + j0 + r)*24 + k];
    }
    if (t < 96) ws2s[t] = Ws2[t];
    const float bs2v = bs2[0];
    __syncthreads();

    for (int e = t; e < 1536; e += 256){
        int ktl = e >> 9, ww = (e >> 6) & 7, nt = (e >> 5) & 1, ln = e & 31;
        int gg = ln >> 2, tt = ln & 3;
        int col = ww*16 + nt*8 + gg;
        int k0 = ktl*8 + tt, k1 = k0 + 4;
        uint2 u;
        u.x = f2tf32(Zi_s[col*25 + k0]);
        u.y = f2tf32(Zi_s[col*25 + k1]);
        Bzi[e] = u;
    }

    for (int jj = 0; jj < JT; jj++){
        __syncthreads();
        if (t < 96) Cj_s[t] = g_Cj[(size_t)(base + j0 + jj)*96 + t];
        {
            const float* zj = &Zj_s[jj*25];
            #pragma unroll
            for (int q = 0; q < 12; q++){
                int e = t + q*256;
                int kt = e >> 9, ww = (e >> 6) & 7, nt = (e >> 5) & 1, ln = e & 31;
                int gg = ln >> 2, tt = ln & 3;
                int col = ww*16 + nt*8 + gg;
                int k0 = kt*8 + tt, k1 = k0 + 4;
                const float* zi = &Zi_s[col*25];
                float f0, f1;
                if (kt < 3){ f0 = zj[k0]*zi[k0]; f1 = zj[k1]*zi[k1]; }
                else { f0 = fabsf(zj[k0-24] - zi[k0-24]); f1 = fabsf(zj[k1-24] - zi[k1-24]); }
                uint2 u; u.x = f2tf32(f0); u.y = f2tf32(f1);
                Bdyn[e] = u;
            }
        }
        __syncthreads();

        u32 bf[2][9][2];
        #pragma unroll
        for (int nt = 0; nt < 2; nt++){
            #pragma unroll
            for (int kt = 0; kt < 6; kt++){
                uint2 u = Bdyn[((kt*8 + w)*2 + nt)*32 + lane];
                bf[nt][kt][0] = u.x; bf[nt][kt][1] = u.y;
            }
            #pragma unroll
            for (int kt = 6; kt < 9; kt++){
                uint2 u = Bzi[(((kt-6)*8 + w)*2 + nt)*32 + lane];
                bf[nt][kt][0] = u.x; bf[nt][kt][1] = u.y;
            }
        }

        float pA[4] = {0.f, 0.f, 0.f, 0.f};
        #pragma unroll
        for (int mt = 0; mt < 6; mt++){
            uint4 af[9];
            #pragma unroll
            for (int kt = 0; kt < 9; kt++) af[kt] = Asw[(mt*9 + kt)*32 + lane];
            const float wsa = ws2s[mt*16 + g],  wsb = ws2s[mt*16 + g + 8];
            const float cja = Cj_s[mt*16 + g],  cjb = Cj_s[mt*16 + g + 8];
            #pragma unroll
            for (int nt = 0; nt < 2; nt++){
                float d0 = 0.f, d1 = 0.f, d2 = 0.f, d3 = 0.f;
                #pragma unroll
                for (int kt = 0; kt < 9; kt++)
                    mma_tf32(d0, d1, d2, d3,
                             af[kt].x, af[kt].y, af[kt].z, af[kt].w,
                             bf[nt][kt][0], bf[nt][kt][1]);
                float v0 = fmaxf(d0 + cja, 0.f);
                float v1 = fmaxf(d1 + cja, 0.f);
                float v2 = fmaxf(d2 + cjb, 0.f);
                float v3 = fmaxf(d3 + cjb, 0.f);
                pA[nt*2]   = fmaf(wsa, v0, fmaf(wsb, v2, pA[nt*2]));
                pA[nt*2+1] = fmaf(wsa, v1, fmaf(wsb, v3, pA[nt*2+1]));
            }
        }
        #pragma unroll
        for (int q = 0; q < 4; q++){
            pA[q] += __shfl_xor_sync(0xffffffffu, pA[q], 4);
            pA[q] += __shfl_xor_sync(0xffffffffu, pA[q], 8);
            pA[q] += __shfl_xor_sync(0xffffffffu, pA[q], 16);
        }
        if (g == 0){
            float* dst = &g_P[(size_t)(base + j0 + jj)*Sn + i0 + w*16];
            *(float2*)(dst + 2*t4)     = make_float2(pA[0] + bs2v, pA[1] + bs2v);
            *(float2*)(dst + 8 + 2*t4) = make_float2(pA[2] + bs2v, pA[3] + bs2v);
        }
    }
}

// =================== kernel 3: masked softmax over i (in place) ===================
__global__ __launch_bounds__(256) void k_softmax(const float* __restrict__ mask){
    const int r = blockIdx.x;
    const int b = r / Sn;
    float* row = g_P + (size_t)r*Sn;
    const float* mrow = mask + (size_t)b*Sn;
    const int t = threadIdx.x;
    __shared__ float red[256];

    float vals[4]; float mx = -3.402823466e38f;
    #pragma unroll
    for (int q = 0; q < 4; q++){
        int i = t + q*256;
        float v = row[i] + (1.0f - mrow[i]) * (-3.402823466e38f);
        vals[q] = v; mx = fmaxf(mx, v);
    }
    red[t] = mx; __syncthreads();
    for (int s = 128; s > 0; s >>= 1){ if (t < s) red[t] = fmaxf(red[t], red[t+s]); __syncthreads(); }
    mx = red[0]; __syncthreads();

    float sum = 0.f;
    #pragma unroll
    for (int q = 0; q < 4; q++){ vals[q] = __expf(vals[q] - mx); sum += vals[q]; }
    red[t] = sum; __syncthreads();
    for (int s = 128; s > 0; s >>= 1){ if (t < s) red[t] += red[t+s]; __syncthreads(); }
    float inv = 1.0f / red[0];
    #pragma unroll
    for (int q = 0; q < 4; q++) row[t + q*256] = vals[q] * inv;
}

// =================== tf32 tensor-core GEMM, tile 64m x 128n ===================
// 256 thr = 8 warps; warp w owns cols [n0+w*16, +16) (nt=0,1), all 64 m rows (mt=0..3).
// K-chunk 16 (2 kt of 8). Double-buffered fragment-staged smem.
// MODE 0: ctx partial = P[:, ks] @ Hi[ks, :]            (K=512 per half)
// MODE 1: h1 partial  = feat[:, ks] @ Wv1[:, ks]^T      (K=1152 per half)
// MODE 2: out = alpha*( relu(h1A+h1B+bv1) @ Wv2^T + bv2 )  (K=768)
template<int MODE>
__global__ __launch_bounds__(256) void k_gemm_t(
    const float* __restrict__ BW,
    const float* __restrict__ Hj,
    const float* __restrict__ bias,    // MODE2: bv1
    const float* __restrict__ bias2,   // MODE2: bv2
    const float* __restrict__ alpha_p,
    float* __restrict__ Cout)
{
    constexpr int KH = (MODE == 0) ? 512 : (MODE == 1) ? 1152 : 768;
    constexpr int T  = KH / 16;
    constexpr int KW = (MODE == 1) ? 2304 : 768;

    __shared__ __align__(16) uint4 Af[2][2][4][32];     // [buf][kt][mt][lane]
    __shared__ __align__(16) uint2 Bf[2][2][8][2][32];  // [buf][kt][w][nt][lane]
    u32* Afu = (u32*)Af;
    u32* Bfu = (u32*)Bf;

    const int t  = threadIdx.x;
    const int n0 = blockIdx.x * 128;
    const int m0 = blockIdx.y * 64;
    int b = 0, ks = 0;
    if (MODE == 0){ b = blockIdx.z >> 1; ks = blockIdx.z & 1; }
    if (MODE == 1){ ks = blockIdx.z; }
    const int rowbase = (MODE == 0) ? b*Sn + m0 : m0;
    const int kbase   = ks * KH;

    const int w = t >> 5, lane = t & 31;
    const int g = lane >> 2, t4 = lane & 3;

    // ---- staging coords ----
    const int amr = t >> 2, aq = t & 3;           // A: row, k-quad
    const int bkl = t >> 4, bnq = t & 15;         // B NN: k-row, n-octet
    const int bnr = t >> 1, bkh = t & 1;          // B NT: n-row, k-half

    const float* ArowP  = g_P    + (size_t)(rowbase + amr)*Sn + kbase;
    const float* ArowCA = g_ctxA + (size_t)(rowbase + amr)*Hn;
    const float* ArowCB = g_ctxB + (size_t)(rowbase + amr)*Hn;
    const float* ArowH  = (MODE == 1) ? (Hj + (size_t)(rowbase + amr)*Hn) : (const float*)0;
    const float* ArowA  = g_h1A  + (size_t)(rowbase + amr)*Hn;
    const float* ArowB  = g_h1B  + (size_t)(rowbase + amr)*Hn;
    const float* Bsrc   = (MODE == 0) ? (BW + (size_t)b*Sn*Hn) : BW;

    float4 ra;           // A: 4 floats (rows amr, k quad aq)
    float4 rb0, rb1;     // B: 8 floats

    auto ldg = [&](int ck){
        const int kb = ck * 16;
        // ---- A ----
        if (MODE == 0){
            ra = *(const float4*)(ArowP + kb + aq*4);
        } else if (MODE == 2){
            const int fo = kb + aq*4;
            float4 xa = *(const float4*)(ArowA + fo);
            float4 xb = *(const float4*)(ArowB + fo);
            float4 bb = *(const float4*)(bias + fo);
            ra = make_float4(fmaxf(xa.x+xb.x+bb.x,0.f), fmaxf(xa.y+xb.y+bb.y,0.f),
                             fmaxf(xa.z+xb.z+bb.z,0.f), fmaxf(xa.w+xb.w+bb.w,0.f));
        } else {
            const int fo = kbase + kb + aq*4;
            if (fo < 768){
                float4 c = *(const float4*)(ArowCA + fo);
                float4 d = *(const float4*)(ArowCB + fo);
                ra = make_float4(c.x+d.x, c.y+d.y, c.z+d.z, c.w+d.w);
            } else if (fo < 1536){
                ra = *(const float4*)(ArowH + fo - 768);
            } else {
                const int go = fo - 1536;
                float4 c = *(const float4*)(ArowCA + go);
                float4 d = *(const float4*)(ArowCB + go);
                float4 h = *(const float4*)(ArowH + go);
                ra = make_float4((c.x+d.x)*h.x, (c.y+d.y)*h.y, (c.z+d.z)*h.z, (c.w+d.w)*h.w);
            }
        }
        // ---- B ----
        if (MODE == 0){
            const float* s = Bsrc + (size_t)(kbase + kb + bkl)*Hn + n0 + bnq*8;
            rb0 = *(const float4*)s; rb1 = *(const float4*)(s + 4);
        } else {
            const float* s = Bsrc + (size_t)(n0 + bnr)*KW + kbase + kb + bkh*8;
            rb0 = *(const float4*)s; rb1 = *(const float4*)(s + 4);
        }
    };

    auto sts = [&](int buf){
        // A scatter: value at (m=amr, k=aq*4+c)
        {
            const int mt = amr >> 4, r8 = (amr >> 3) & 1, gg = amr & 7;
            const float av[4] = {ra.x, ra.y, ra.z, ra.w};
            #pragma unroll
            for (int c = 0; c < 4; c++){
                int k = aq*4 + c;
                int kt = k >> 3, hk = (k >> 2) & 1, tt = k & 3;
                int ln = gg*4 + tt;
                Afu[((((buf*2 + kt)*4 + mt)*32) + ln)*4 + hk*2 + r8] = f2tf32(av[c]);
            }
        }
        // B scatter
        const float bv[8] = {rb0.x, rb0.y, rb0.z, rb0.w, rb1.x, rb1.y, rb1.z, rb1.w};
        if (MODE == 0){
            // value at (k = bkl, n = bnq*8 + c)
            const int k = bkl;
            const int kt = k >> 3, h = (k >> 2) & 1, tt = k & 3;
            #pragma unroll
            for (int c = 0; c < 8; c++){
                int n = bnq*8 + c;
                int ww = n >> 4, nt = (n >> 3) & 1, gg = n & 7;
                int ln = gg*4 + tt;
                Bfu[(((((buf*2 + kt)*8 + ww)*2 + nt)*32) + ln)*2 + h] = f2tf32(bv[c]);
            }
        } else {
            // value at (n = bnr, k = bkh*8 + c)
            const int n = bnr;
            const int ww = n >> 4, nt = (n >> 3) & 1, gg = n & 7;
            #pragma unroll
            for (int c = 0; c < 8; c++){
                int k = bkh*8 + c;
                int kt = k >> 3, h = (k >> 2) & 1, tt = k & 3;
                int ln = gg*4 + tt;
                Bfu[(((((buf*2 + kt)*8 + ww)*2 + nt)*32) + ln)*2 + h] = f2tf32(bv[c]);
            }
        }
    };

    float acc[4][2][4];
    #pragma unroll
    for (int mt = 0; mt < 4; mt++)
        #pragma unroll
        for (int nt = 0; nt < 2; nt++)
            #pragma unroll
            for (int q = 0; q < 4; q++) acc[mt][nt][q] = 0.f;

    ldg(0); sts(0); __syncthreads();

    for (int tt = 0; tt < T; tt++){
        const int cur = tt & 1;
        if (tt + 1 < T) ldg(tt + 1);
        #pragma unroll
        for (int kt = 0; kt < 2; kt++){
            uint2 bfr[2];
            bfr[0] = Bf[cur][kt][w][0][lane];
            bfr[1] = Bf[cur][kt][w][1][lane];
            uint4 afr[4];
            #pragma unroll
            for (int mt = 0; mt < 4; mt++) afr[mt] = Af[cur][kt][mt][lane];
            #pragma unroll
            for (int mt = 0; mt < 4; mt++)
                #pragma unroll
                for (int nt = 0; nt < 2; nt++)
                    mma_tf32(acc[mt][nt][0], acc[mt][nt][1], acc[mt][nt][2], acc[mt][nt][3],
                             afr[mt].x, afr[mt].y, afr[mt].z, afr[mt].w,
                             bfr[nt].x, bfr[nt].y);
        }
        if (tt + 1 < T) sts(cur ^ 1);
        __syncthreads();
    }

    // ---- epilogue ----
    const float alpha = (MODE == 2) ? alpha_p[0] : 1.0f;
    const int wbase = n0 + w*16;
    float2 badd[2];
    if (MODE == 2){
        badd[0] = *(const float2*)(bias2 + wbase + 2*t4);
        badd[1] = *(const float2*)(bias2 + wbase + 8 + 2*t4);
    }
    #pragma unroll
    for (int mt = 0; mt < 4; mt++){
        #pragma unroll
        for (int nt = 0; nt < 2; nt++){
            const int col = wbase + nt*8 + 2*t4;
            float2 v0 = make_float2(acc[mt][nt][0], acc[mt][nt][1]);   // row mt*16+g
            float2 v1 = make_float2(acc[mt][nt][2], acc[mt][nt][3]);   // row mt*16+g+8
            if (MODE == 2){
                v0.x = (v0.x + badd[nt].x) * alpha; v0.y = (v0.y + badd[nt].y) * alpha;
                v1.x = (v1.x + badd[nt].x) * alpha; v1.y = (v1.y + badd[nt].y) * alpha;
            }
            float* dstbuf;
            if      (MODE == 0) dstbuf = (ks == 0 ? g_ctxA : g_ctxB);
            else if (MODE == 1) dstbuf = (ks == 0 ? g_h1A  : g_h1B );
            else                dstbuf = Cout;
            *(float2*)(dstbuf + (size_t)(rowbase + mt*16 + g)*Hn + col)     = v0;
            *(float2*)(dstbuf + (size_t)(rowbase + mt*16 + g + 8)*Hn + col) = v1;
        }
    }
}

// =============================== launch ===============================
extern "C" void kernel_launch(void* const* d_in, const int* in_sizes, int n_in,
                              void* d_out, int out_size)
{
    const float* Hj    = (const float*)d_in[0];
    const float* Hi    = (const float*)d_in[1];
    const float* mask  = (const float*)d_in[2];
    const float* Wpj   = (const float*)d_in[3];
    const float* Wpi   = (const float*)d_in[4];
    const float* Ws1   = (const float*)d_in[5];
    const float* bs1   = (const float*)d_in[6];
    const float* Ws2   = (const float*)d_in[7];
    const float* bs2   = (const float*)d_in[8];
    const float* Wv1   = (const float*)d_in[9];
    const float* bv1   = (const float*)d_in[10];
    const float* Wv2   = (const float*)d_in[11];
    const float* bv2   = (const float*)d_in[12];
    const float* alpha = (const float*)d_in[13];
    float* out = (float*)d_out;

    cudaFuncSetAttribute(k_pair_mma, cudaFuncAttributeMaxDynamicSharedMemorySize, SMEM_PAIR);

    k_proj<<<Bn*Sn, 256>>>(Hj, Hi, Wpj, Wpi, Ws1, bs1);

    dim3 gp(Sn/IT, Sn/JT, Bn);
    k_pair_mma<<<gp, 256, SMEM_PAIR>>>(Ws1, Ws2, bs2);

    k_softmax<<<Bn*Sn, 256>>>(mask);

    dim3 g0(Hn/128, Sn/64, Bn*2);
    k_gemm_t<0><<<g0, 256>>>(Hi, nullptr, nullptr, nullptr, nullptr, nullptr);

    dim3 g1(Hn/128, (Bn*Sn)/64, 2);
    k_gemm_t<1><<<g1, 256>>>(Wv1, Hj, nullptr, nullptr, nullptr, nullptr);

    dim3 g2(Hn/128, (Bn*Sn)/64, 1);
    k_gemm_t<2><<<g2, 256>>>(Wv2, nullptr, bv1, bv2, alpha, out);
}